// round 12
// baseline (speedup 1.0000x reference)
#include <cuda_runtime.h>
#include <math.h>
#include <stdint.h>

// Problem constants
#define BB   8
#define SS   1024
#define EE   1024
#define HH   16
#define FF   4096
#define MR   (BB*SS)      // 8192 rows

// -------- scratch (static device globals; no runtime allocation) --------
__device__ float g_qkv[(size_t)MR * 3 * EE];
__device__ float g_ctx[(size_t)MR * EE];
__device__ float g_t1 [(size_t)MR * EE];
__device__ float g_h  [(size_t)MR * EE];
__device__ float g_ffa[(size_t)MR * FF];
__device__ float g_t2 [(size_t)MR * EE];
__device__ float g_kadd[MR];
__device__ float g_kneg[MR];
__device__ float g_wqkvT[(size_t)3 * EE * EE];
__device__ float g_woutT[(size_t)EE * EE];
__device__ float g_winT [(size_t)FF * EE];
__device__ float g_wffoT[(size_t)EE * FF];

// ======================= PTX helpers =======================
__device__ __forceinline__ uint32_t smem_u32(const void* p) {
    uint32_t a;
    asm("{ .reg .u64 t; cvta.to.shared.u64 t, %1; cvt.u32.u64 %0, t; }"
        : "=r"(a) : "l"(p));
    return a;
}
__device__ __forceinline__ void cp16(uint32_t dst, const void* src) {
    asm volatile("cp.async.cg.shared.global [%0], [%1], 16;" :: "r"(dst), "l"(src));
}
#define CP_COMMIT() asm volatile("cp.async.commit_group;" ::: "memory")
#define CP_WAIT0()  asm volatile("cp.async.wait_group 0;" ::: "memory")

__device__ __forceinline__ void ldsm4(uint32_t& r0, uint32_t& r1, uint32_t& r2, uint32_t& r3,
                                      uint32_t addr) {
    asm volatile("ldmatrix.sync.aligned.m8n8.x4.shared.b16 {%0,%1,%2,%3}, [%4];"
                 : "=r"(r0), "=r"(r1), "=r"(r2), "=r"(r3) : "r"(addr));
}
__device__ __forceinline__ uint32_t f2tf32(uint32_t x) {
    uint32_t y;
    asm("cvt.rna.tf32.f32 %0, %1;" : "=r"(y) : "f"(__uint_as_float(x)));
    return y;
}
__device__ __forceinline__ float rnd_tf32(float v) {
    uint32_t b;
    asm("cvt.rna.tf32.f32 %0, %1;" : "=r"(b) : "f"(v));
    return __uint_as_float(b);
}
__device__ __forceinline__ void mma_tf32(float* c, const uint32_t* a, uint32_t b0, uint32_t b1) {
    asm volatile(
        "mma.sync.aligned.m16n8k8.row.col.f32.tf32.tf32.f32 "
        "{%0,%1,%2,%3}, {%4,%5,%6,%7}, {%8,%9}, {%0,%1,%2,%3};"
        : "+f"(c[0]), "+f"(c[1]), "+f"(c[2]), "+f"(c[3])
        : "r"(a[0]), "r"(a[1]), "r"(a[2]), "r"(a[3]), "r"(b0), "r"(b1));
}

// ======================= weight transpose + tf32 round =======================
__global__ void transpose_kernel(const float* __restrict__ W, float* __restrict__ WT,
                                 int K, int N) {
    __shared__ float t[32][33];
    int n0 = blockIdx.x * 32, k0 = blockIdx.y * 32;
    int tx = threadIdx.x, ty = threadIdx.y;
#pragma unroll
    for (int i = 0; i < 32; i += 8)
        t[ty + i][tx] = W[(size_t)(k0 + ty + i) * N + n0 + tx];
    __syncthreads();
#pragma unroll
    for (int i = 0; i < 32; i += 8) {
        float v = t[tx][ty + i];
        WT[(size_t)(n0 + ty + i) * K + k0 + tx] = rnd_tf32(v);
    }
}

// ======================= mask precompute =======================
__global__ void mask_kernel(const int* __restrict__ am, const int* __restrict__ tt) {
    int i = blockIdx.x * 256 + threadIdx.x;
    if (i >= MR) return;
    bool a  = (am[i] != 0);
    bool qm = (tt[i] == 1) || (!a) || ((i & (SS - 1)) == 0);
    g_kadd[i] = a  ? 1.f : 0.f;
    g_kneg[i] = qm ? 1.f : 0.f;
}

// ======================= tf32 tensor-core GEMM v3 =======================
// 256 threads / 8 warps (2m x 4n), warp tile 64x64. BM=128, BN=256, BK=32, 4 stages.
// mode: bit0 = exact GELU; bit1 = round output to tf32 (for QKV)
#define GBM 128
#define GBN 256
#define GBK 32
#define GSTAGE_A (GBM * GBK * 4)            // 16 KB
#define GSTAGE_B (GBN * GBK * 4)            // 32 KB
#define GSTAGE_BYTES (GSTAGE_A + GSTAGE_B)  // 48 KB
#define GSTAGES 4
#define GEMM_SMEM_DYN (GSTAGES * GSTAGE_BYTES)   // 192 KB

__global__ __launch_bounds__(256, 1) void mma_gemm(
    const float* __restrict__ A, const float* __restrict__ BT,
    const float* __restrict__ bias, const float* __restrict__ res,
    float* __restrict__ C, int M, int N, int K, int mode)
{
    extern __shared__ char dyn_smem[];
    uint32_t sbase = smem_u32(dyn_smem);
    int tid = threadIdx.x, lane = tid & 31, wid = tid >> 5;
    int wm = wid >> 2, wn = wid & 3;            // warp tile: rows wm*64, cols wn*64
    int bm = blockIdx.y * GBM, bn = blockIdx.x * GBN;

    float c[4][8][4];
#pragma unroll
    for (int mi = 0; mi < 4; mi++)
#pragma unroll
        for (int j = 0; j < 8; j++)
#pragma unroll
            for (int q = 0; q < 4; q++) c[mi][j][q] = 0.f;

    int T = K / GBK;

    auto load_tile = [&](int t, int s) {
        int k0 = t * GBK;
        uint32_t sA = sbase + s * GSTAGE_BYTES;
        uint32_t sB = sA + GSTAGE_A;
#pragma unroll
        for (int i = 0; i < 4; i++) {            // A: 1024 granules / 256 thr
            int g = tid + i * 256;
            int row = g >> 3, ch = g & 7;
            cp16(sA + row * 128 + ((ch ^ (row & 7)) << 4),
                 A + (size_t)(bm + row) * K + k0 + ch * 4);
        }
#pragma unroll
        for (int i = 0; i < 8; i++) {            // B: 2048 granules
            int g = tid + i * 256;
            int row = g >> 3, ch = g & 7;
            cp16(sB + row * 128 + ((ch ^ (row & 7)) << 4),
                 BT + (size_t)(bn + row) * K + k0 + ch * 4);
        }
    };

    load_tile(0, 0); CP_COMMIT();
    load_tile(1, 1); CP_COMMIT();
    load_tile(2, 2); CP_COMMIT();

    for (int t = 0; t < T; t++) {
        asm volatile("cp.async.wait_group 2;" ::: "memory");
        __syncthreads();
        if (t + 3 < T) load_tile(t + 3, (t + 3) & 3);
        CP_COMMIT();

        int s = t & 3;
        uint32_t sA = sbase + s * GSTAGE_BYTES;
        uint32_t sB = sA + GSTAGE_A;

#pragma unroll
        for (int p = 0; p < 2; p++) {
            uint32_t a[4][2][4];
#pragma unroll
            for (int mi = 0; mi < 4; mi++)
#pragma unroll
                for (int kk = 0; kk < 2; kk++) {
                    int ks = p * 2 + kk;
                    int r = wm * 64 + mi * 16 + ((lane >> 3) & 1) * 8 + (lane & 7);
                    int ch = ks * 2 + (lane >> 4);
                    ldsm4(a[mi][kk][0], a[mi][kk][1], a[mi][kk][2], a[mi][kk][3],
                          sA + r * 128 + ((ch ^ (r & 7)) << 4));
#pragma unroll
                    for (int q = 0; q < 4; q++) a[mi][kk][q] = f2tf32(a[mi][kk][q]);
                }
#pragma unroll
            for (int j = 0; j < 8; j++) {
                uint32_t b0, b1, b2, b3;
                int r = wn * 64 + j * 8 + (lane & 7);
                int ch = p * 4 + (lane >> 3);
                ldsm4(b0, b1, b2, b3, sB + r * 128 + ((ch ^ (r & 7)) << 4));
#pragma unroll
                for (int mi = 0; mi < 4; mi++) {
                    mma_tf32(c[mi][j], a[mi][0], b0, b1);
                    mma_tf32(c[mi][j], a[mi][1], b2, b3);
                }
            }
        }
    }

    // ---- epilogue ----
#pragma unroll
    for (int mi = 0; mi < 4; mi++) {
        int r0 = bm + wm * 64 + mi * 16 + (lane >> 2);
#pragma unroll
        for (int half = 0; half < 2; half++) {
            int r = r0 + half * 8;
            float* Crow = C + (size_t)r * N;
            const float* Rrow = res ? res + (size_t)r * N : nullptr;
#pragma unroll
            for (int j = 0; j < 8; j++) {
                int col = bn + wn * 64 + j * 8 + (lane & 3) * 2;
                float v0 = c[mi][j][half * 2 + 0] + bias[col];
                float v1 = c[mi][j][half * 2 + 1] + bias[col + 1];
                if (Rrow) { v0 += Rrow[col]; v1 += Rrow[col + 1]; }
                if (mode & 1) {
                    v0 = 0.5f * v0 * (1.0f + erff(v0 * 0.70710678118654752f));
                    v1 = 0.5f * v1 * (1.0f + erff(v1 * 0.70710678118654752f));
                }
                if (mode & 2) { v0 = rnd_tf32(v0); v1 = rnd_tf32(v1); }
                *(float2*)(Crow + col) = make_float2(v0, v1);
            }
        }
    }
}

// ======================= Pipelined flash attention v2 (tf32 mma.sync) =======================
// 128 thr / 4 warps, 2 CTAs/SM. BQ=128 (warp owns 32 q-rows = 2 m16 tiles), BK=64.
// Halves smem bytes per mma vs v1 (L1-bandwidth was the binding roofline).
#define AQ 128
#define AK 64
#define APITCH 68
#define AROW (APITCH * 4)          // 272 B row pitch
#define ATTN_SMEM_DYN ((AQ * APITCH + 4 * AK * APITCH) * 4)

__global__ __launch_bounds__(128, 2) void attn_mma(
    const float* __restrict__ QKV, float* __restrict__ CTX)
{
    extern __shared__ float as[];
    float* sQ = as;                                // 128 x 68
    float* sK0 = sQ + AQ * APITCH;                 // stage 0 K
    float* sK1 = sK0 + AK * APITCH;                // stage 1 K
    float* sV0 = sK1 + AK * APITCH;                // stage 0 VT
    float* sV1 = sV0 + AK * APITCH;                // stage 1 VT
    __shared__ float sAdd[2][AK], sNeg[2][AK];

    uint32_t uQ = smem_u32(sQ);
    uint32_t uK[2] = { smem_u32(sK0), smem_u32(sK1) };
    uint32_t uV[2] = { smem_u32(sV0), smem_u32(sV1) };
    uint32_t uA[2] = { smem_u32(&sAdd[0][0]), smem_u32(&sAdd[1][0]) };
    uint32_t uN[2] = { smem_u32(&sNeg[0][0]), smem_u32(&sNeg[1][0]) };
    float* sVT[2] = { sV0, sV1 };

    int tid = threadIdx.x, lane = tid & 31, wid = tid >> 5;   // wid 0..3
    int b = blockIdx.z, h = blockIdx.y, q0 = blockIdx.x * AQ;
    int wq0 = wid * 32;                            // warp's 32-row q band

    const float* Qb = QKV + (size_t)b * SS * 3072 + h * 64;
    const float* Kb = Qb + 1024;
    const float* Vb = Qb + 2048;
    const float* madd = g_kadd + b * SS;
    const float* mneg = g_kneg + b * SS;

    int lr = lane >> 2, sub = lane & 3;
    uint32_t qbase = lane & ~3u;
    int phalf = sub >> 1, podd = sub & 1;

    // V-transpose task mapping: quad vq handles tasks (kg, dc), 8 per iter
    int vq = tid >> 2;                             // 0..31

    // ---------------- prologue ----------------
#pragma unroll
    for (int i = 0; i < 16; i++) {                 // Q: 2048 granules / 128 thr
        int g = tid + i * 128, r = g >> 4, c4 = g & 15;
        cp16(uQ + r * AROW + c4 * 16, Qb + (size_t)(q0 + r) * 3072 + c4 * 4);
    }
#pragma unroll
    for (int i = 0; i < 8; i++) {                  // K0: 1024 granules
        int g = tid + i * 128, r = g >> 4, c4 = g & 15;
        cp16(uK[0] + r * AROW + c4 * 16, Kb + (size_t)r * 3072 + c4 * 4);
    }
    if (tid < 16) cp16(uA[0] + tid * 16, madd + tid * 4);
    else if (tid < 32) cp16(uN[0] + (tid - 16) * 16, mneg + (tid - 16) * 4);
    CP_COMMIT();

    float4 pv[8];
#pragma unroll
    for (int it = 0; it < 8; it++) {
        int task = vq + it * 32;
        int kg = task & 15, dc = task >> 4;
        pv[it] = *(const float4*)(Vb + (size_t)(kg * 4 + sub) * 3072 + dc * 4);
    }

    float amq[2][2];
#pragma unroll
    for (int mi = 0; mi < 2; mi++) {
        amq[mi][0] = madd[q0 + wq0 + mi * 16 + lr];
        amq[mi][1] = madd[q0 + wq0 + mi * 16 + lr + 8];
    }

    CP_WAIT0();
    __syncthreads();

    // build VT stage 0 from pv
#pragma unroll
    for (int it = 0; it < 8; it++) {
        int task = vq + it * 32;
        int kg = task & 15, dc = task >> 4;
        float a0 = pv[it].x, a1 = pv[it].y, a2 = pv[it].z, a3 = pv[it].w;
        float t0, t1, t2, t3;
#pragma unroll
        for (int j = 0; j < 4; j++) {
            int sidx = (sub + j) & 3;
            float sval = sidx == 0 ? a0 : sidx == 1 ? a1 : sidx == 2 ? a2 : a3;
            int i = (sub - j) & 3;
            float r = __shfl_sync(0xffffffffu, sval, qbase | i);
            if (i == 0) t0 = r; else if (i == 1) t1 = r; else if (i == 2) t2 = r; else t3 = r;
        }
        *(float4*)(sVT[0] + (dc * 4 + sub) * APITCH + kg * 4) = make_float4(t0, t1, t2, t3);
    }
    __syncthreads();

    // ---------------- mainloop ----------------
    float m[2][2], l[2][2];
#pragma unroll
    for (int mi = 0; mi < 2; mi++) {
        m[mi][0] = -INFINITY; m[mi][1] = -INFINITY;
        l[mi][0] = 0.f; l[mi][1] = 0.f;
    }
    float o[2][8][4];
#pragma unroll
    for (int mi = 0; mi < 2; mi++)
#pragma unroll
        for (int j = 0; j < 8; j++)
#pragma unroll
            for (int q = 0; q < 4; q++) o[mi][j][q] = 0.f;

    const int T = SS / AK;
#pragma unroll 1
    for (int t = 0; t < T; t++) {
        int st = t & 1, sn = st ^ 1;
        bool has_next = (t + 1) < T;
        int k0n = has_next ? (t + 1) * AK : 0;

        // prefetch K[t+1] + masks[t+1] (cp.async) and V[t+1] (LDG regs)
        if (has_next) {
#pragma unroll
            for (int i = 0; i < 8; i++) {
                int g = tid + i * 128, r = g >> 4, c4 = g & 15;
                cp16(uK[sn] + r * AROW + c4 * 16, Kb + (size_t)(k0n + r) * 3072 + c4 * 4);
            }
            if (tid < 16) cp16(uA[sn] + tid * 16, madd + k0n + tid * 4);
            else if (tid < 32) cp16(uN[sn] + (tid - 16) * 16, mneg + k0n + (tid - 16) * 4);
        }
        CP_COMMIT();
        if (has_next) {
#pragma unroll
            for (int it = 0; it < 8; it++) {
                int task = vq + it * 32;
                int kg = task & 15, dc = task >> 4;
                pv[it] = *(const float4*)(Vb + (size_t)(k0n + kg * 4 + sub) * 3072 + dc * 4);
            }
        }

        // ===== S = Q @ K^T =====
        float c[2][8][4];
#pragma unroll
        for (int mi = 0; mi < 2; mi++)
#pragma unroll
            for (int j = 0; j < 8; j++)
#pragma unroll
                for (int q = 0; q < 4; q++) c[mi][j][q] = 0.f;

#pragma unroll
        for (int p = 0; p < 4; p++) {
            uint32_t a[2][2][4];
#pragma unroll
            for (int mi = 0; mi < 2; mi++)
#pragma unroll
                for (int kk = 0; kk < 2; kk++) {
                    int ks = p * 2 + kk;
                    int r = wq0 + mi * 16 + ((lane >> 3) & 1) * 8 + (lane & 7);
                    int ch = ks * 2 + (lane >> 4);
                    ldsm4(a[mi][kk][0], a[mi][kk][1], a[mi][kk][2], a[mi][kk][3],
                          uQ + r * AROW + ch * 16);
                }
#pragma unroll
            for (int j = 0; j < 8; j++) {
                uint32_t b0, b1, b2, b3;
                int r = j * 8 + (lane & 7);
                int ch = p * 4 + (lane >> 3);
                ldsm4(b0, b1, b2, b3, uK[st] + r * AROW + ch * 16);
#pragma unroll
                for (int mi = 0; mi < 2; mi++) {
                    mma_tf32(c[mi][j], a[mi][0], b0, b1);
                    mma_tf32(c[mi][j], a[mi][1], b2, b3);
                }
            }
        }

        // ===== mask + online softmax (per m-tile) =====
        float alpha[2][2];
#pragma unroll
        for (int mi = 0; mi < 2; mi++) {
            float mt0 = -INFINITY, mt1 = -INFINITY;
#pragma unroll
            for (int j = 0; j < 8; j++) {
                int col = j * 8 + sub * 2;
                float ka0 = sAdd[st][col], ka1 = sAdd[st][col + 1];
                float kn0 = sNeg[st][col], kn1 = sNeg[st][col + 1];
                c[mi][j][0] = (kn0 != 0.f) ? -1e30f : c[mi][j][0] * 0.125f + amq[mi][0] * ka0;
                c[mi][j][1] = (kn1 != 0.f) ? -1e30f : c[mi][j][1] * 0.125f + amq[mi][0] * ka1;
                c[mi][j][2] = (kn0 != 0.f) ? -1e30f : c[mi][j][2] * 0.125f + amq[mi][1] * ka0;
                c[mi][j][3] = (kn1 != 0.f) ? -1e30f : c[mi][j][3] * 0.125f + amq[mi][1] * ka1;
                mt0 = fmaxf(mt0, fmaxf(c[mi][j][0], c[mi][j][1]));
                mt1 = fmaxf(mt1, fmaxf(c[mi][j][2], c[mi][j][3]));
            }
            mt0 = fmaxf(mt0, __shfl_xor_sync(0xffffffffu, mt0, 1));
            mt0 = fmaxf(mt0, __shfl_xor_sync(0xffffffffu, mt0, 2));
            mt1 = fmaxf(mt1, __shfl_xor_sync(0xffffffffu, mt1, 1));
            mt1 = fmaxf(mt1, __shfl_xor_sync(0xffffffffu, mt1, 2));

            float mn0 = fmaxf(m[mi][0], mt0), mn1 = fmaxf(m[mi][1], mt1);
            alpha[mi][0] = __expf(m[mi][0] - mn0);
            alpha[mi][1] = __expf(m[mi][1] - mn1);
            m[mi][0] = mn0; m[mi][1] = mn1;

            float s0 = 0.f, s1 = 0.f;
#pragma unroll
            for (int j = 0; j < 8; j++) {
                c[mi][j][0] = __expf(c[mi][j][0] - mn0);
                c[mi][j][1] = __expf(c[mi][j][1] - mn0);
                c[mi][j][2] = __expf(c[mi][j][2] - mn1);
                c[mi][j][3] = __expf(c[mi][j][3] - mn1);
                s0 += c[mi][j][0] + c[mi][j][1];
                s1 += c[mi][j][2] + c[mi][j][3];
            }
            s0 += __shfl_xor_sync(0xffffffffu, s0, 1);
            s0 += __shfl_xor_sync(0xffffffffu, s0, 2);
            s1 += __shfl_xor_sync(0xffffffffu, s1, 1);
            s1 += __shfl_xor_sync(0xffffffffu, s1, 2);
            l[mi][0] = l[mi][0] * alpha[mi][0] + s0;
            l[mi][1] = l[mi][1] * alpha[mi][1] + s1;

#pragma unroll
            for (int j = 0; j < 8; j++) {
                o[mi][j][0] *= alpha[mi][0]; o[mi][j][1] *= alpha[mi][0];
                o[mi][j][2] *= alpha[mi][1]; o[mi][j][3] *= alpha[mi][1];
            }
        }

        // ===== O += P @ V : P frags via intra-quad shfl from c =====
#pragma unroll
        for (int p = 0; p < 4; p++) {
            uint32_t a_lo[2][4], a_hi[2][4];
#pragma unroll
            for (int mi = 0; mi < 2; mi++)
#pragma unroll
                for (int hh = 0; hh < 2; hh++) {
                    int kc = 2 * p + hh;
                    float v00 = __shfl_sync(0xffffffffu, c[mi][kc][0], qbase + phalf);
                    float v01 = __shfl_sync(0xffffffffu, c[mi][kc][1], qbase + phalf);
                    float v10 = __shfl_sync(0xffffffffu, c[mi][kc][2], qbase + phalf);
                    float v11 = __shfl_sync(0xffffffffu, c[mi][kc][3], qbase + phalf);
                    float v20 = __shfl_sync(0xffffffffu, c[mi][kc][0], qbase + 2 + phalf);
                    float v21 = __shfl_sync(0xffffffffu, c[mi][kc][1], qbase + 2 + phalf);
                    float v30 = __shfl_sync(0xffffffffu, c[mi][kc][2], qbase + 2 + phalf);
                    float v31 = __shfl_sync(0xffffffffu, c[mi][kc][3], qbase + 2 + phalf);
                    uint32_t* a = hh ? a_hi[mi] : a_lo[mi];
                    a[0] = __float_as_uint(podd ? v01 : v00);
                    a[1] = __float_as_uint(podd ? v11 : v10);
                    a[2] = __float_as_uint(podd ? v21 : v20);
                    a[3] = __float_as_uint(podd ? v31 : v30);
                }
#pragma unroll
            for (int j = 0; j < 8; j++) {
                uint32_t b0, b1, b2, b3;
                int r = j * 8 + (lane & 7);
                int ch = p * 4 + (lane >> 3);
                ldsm4(b0, b1, b2, b3, uV[st] + r * AROW + ch * 16);
#pragma unroll
                for (int mi = 0; mi < 2; mi++) {
                    mma_tf32(o[mi][j], a_lo[mi], b0, b1);
                    mma_tf32(o[mi][j], a_hi[mi], b2, b3);
                }
            }
        }

        // ===== build VT[t+1] from pv regs =====
        if (has_next) {
#pragma unroll
            for (int it = 0; it < 8; it++) {
                int task = vq + it * 32;
                int kg = task & 15, dc = task >> 4;
                float a0 = pv[it].x, a1 = pv[it].y, a2 = pv[it].z, a3 = pv[it].w;
                float t0, t1, t2, t3;
#pragma unroll
                for (int j = 0; j < 4; j++) {
                    int sidx = (sub + j) & 3;
                    float sval = sidx == 0 ? a0 : sidx == 1 ? a1 : sidx == 2 ? a2 : a3;
                    int i = (sub - j) & 3;
                    float r = __shfl_sync(0xffffffffu, sval, qbase | i);
                    if (i == 0) t0 = r; else if (i == 1) t1 = r; else if (i == 2) t2 = r; else t3 = r;
                }
                *(float4*)(sVT[sn] + (dc * 4 + sub) * APITCH + kg * 4) = make_float4(t0, t1, t2, t3);
            }
        }

        CP_WAIT0();
        __syncthreads();
    }

    // ---- epilogue ----
#pragma unroll
    for (int mi = 0; mi < 2; mi++) {
        float inv0 = 1.f / l[mi][0], inv1 = 1.f / l[mi][1];
        size_t row0 = (size_t)(b * SS + q0 + wq0 + mi * 16 + lr);
        size_t row1 = row0 + 8;
#pragma unroll
        for (int j = 0; j < 8; j++) {
            int col = h * 64 + j * 8 + sub * 2;
            *(float2*)(CTX + row0 * EE + col) = make_float2(o[mi][j][0] * inv0, o[mi][j][1] * inv0);
            *(float2*)(CTX + row1 * EE + col) = make_float2(o[mi][j][2] * inv1, o[mi][j][3] * inv1);
        }
    }
}

// ======================= LayerNorm =======================
__global__ __launch_bounds__(256) void ln_kernel(
    const float* __restrict__ in, const float* __restrict__ w,
    const float* __restrict__ b, float* __restrict__ out)
{
    int row = blockIdx.x;
    const float* x = in + (size_t)row * EE;
    int tid = threadIdx.x;

    float v[4], s = 0.f, sq = 0.f;
#pragma unroll
    for (int i = 0; i < 4; i++) {
        v[i] = x[tid + i * 256];
        s += v[i];
        sq += v[i] * v[i];
    }
#pragma unroll
    for (int off = 16; off > 0; off >>= 1) {
        s  += __shfl_xor_sync(0xffffffffu, s,  off);
        sq += __shfl_xor_sync(0xffffffffu, sq, off);
    }
    __shared__ float ss[8], ssq[8];
    if ((tid & 31) == 0) { ss[tid >> 5] = s; ssq[tid >> 5] = sq; }
    __syncthreads();
    float ts = 0.f, tsq = 0.f;
#pragma unroll
    for (int wi = 0; wi < 8; wi++) { ts += ss[wi]; tsq += ssq[wi]; }
    float mean = ts * (1.f / EE);
    float var = tsq * (1.f / EE) - mean * mean;
    float rstd = rsqrtf(var + 1e-12f);
    float* y = out + (size_t)row * EE;
#pragma unroll
    for (int i = 0; i < 4; i++) {
        int c = tid + i * 256;
        y[c] = (v[i] - mean) * rstd * w[c] + b[c];
    }
}

// ======================= launch =======================
extern "C" void kernel_launch(void* const* d_in, const int* in_sizes, int n_in,
                              void* d_out, int out_size)
{
    const float* x      = (const float*)d_in[0];
    const int*   am     = (const int*)d_in[1];
    const int*   tt     = (const int*)d_in[2];
    const float* w_qkv  = (const float*)d_in[3];
    const float* b_qkv  = (const float*)d_in[4];
    const float* w_out  = (const float*)d_in[5];
    const float* b_outp = (const float*)d_in[6];
    const float* ln_w   = (const float*)d_in[7];
    const float* ln_b   = (const float*)d_in[8];
    const float* w_in   = (const float*)d_in[9];
    const float* b_in   = (const float*)d_in[10];
    const float* w_ffo  = (const float*)d_in[11];
    const float* b_ffo  = (const float*)d_in[12];
    float* out = (float*)d_out;

    float *qkv, *ctx, *t1, *hb, *ffa, *t2, *wqkvT, *woutT, *winT, *wffoT;
    cudaGetSymbolAddress((void**)&qkv,   g_qkv);
    cudaGetSymbolAddress((void**)&ctx,   g_ctx);
    cudaGetSymbolAddress((void**)&t1,    g_t1);
    cudaGetSymbolAddress((void**)&hb,    g_h);
    cudaGetSymbolAddress((void**)&ffa,   g_ffa);
    cudaGetSymbolAddress((void**)&t2,    g_t2);
    cudaGetSymbolAddress((void**)&wqkvT, g_wqkvT);
    cudaGetSymbolAddress((void**)&woutT, g_woutT);
    cudaGetSymbolAddress((void**)&winT,  g_winT);
    cudaGetSymbolAddress((void**)&wffoT, g_wffoT);

    cudaFuncSetAttribute(attn_mma, cudaFuncAttributeMaxDynamicSharedMemorySize, ATTN_SMEM_DYN);
    cudaFuncSetAttribute(mma_gemm, cudaFuncAttributeMaxDynamicSharedMemorySize, GEMM_SMEM_DYN);

    dim3 tb(32, 8);
    transpose_kernel<<<dim3(3 * EE / 32, EE / 32), tb>>>(w_qkv, wqkvT, EE, 3 * EE);
    mask_kernel<<<MR / 256, 256>>>(am, tt);

    // QKV projection -> output rounded to tf32 (mode=2)
    mma_gemm<<<dim3(3 * EE / GBN, MR / GBM), 256, GEMM_SMEM_DYN>>>(
        x, wqkvT, b_qkv, nullptr, qkv, MR, 3 * EE, EE, 2);
    // attention (pipelined tensor-core flash, 4-warp wide-M variant)
    attn_mma<<<dim3(SS / AQ, HH, BB), 128, ATTN_SMEM_DYN>>>(qkv, ctx);

    transpose_kernel<<<dim3(EE / 32, EE / 32), tb>>>(w_out, woutT, EE, EE);
    // out projection + residual
    mma_gemm<<<dim3(EE / GBN, MR / GBM), 256, GEMM_SMEM_DYN>>>(
        ctx, woutT, b_outp, x, t1, MR, EE, EE, 0);
    // LN -> h
    ln_kernel<<<MR, 256>>>(t1, ln_w, ln_b, hb);

    transpose_kernel<<<dim3(FF / 32, EE / 32), tb>>>(w_in,  winT,  EE, FF);
    // FFN in + GELU
    mma_gemm<<<dim3(FF / GBN, MR / GBM), 256, GEMM_SMEM_DYN>>>(
        hb, winT, b_in, nullptr, ffa, MR, FF, EE, 1);

    transpose_kernel<<<dim3(EE / 32, FF / 32), tb>>>(w_ffo, wffoT, FF, EE);
    // FFN out + residual
    mma_gemm<<<dim3(EE / GBN, MR / GBM), 256, GEMM_SMEM_DYN>>>(
        ffa, wffoT, b_ffo, hb, t2, MR, EE, FF, 0);
    // LN -> out
    ln_kernel<<<MR, 256>>>(t2, ln_w, ln_b, out);
}

// round 15
// speedup vs baseline: 1.1217x; 1.1217x over previous
#include <cuda_runtime.h>
#include <math.h>
#include <stdint.h>

// Problem constants
#define BB   8
#define SS   1024
#define EE   1024
#define HH   16
#define FF   4096
#define MR   (BB*SS)      // 8192 rows

// -------- scratch (static device globals; no runtime allocation) --------
__device__ float g_qkv[(size_t)MR * 3 * EE];
__device__ float g_ctx[(size_t)MR * EE];
__device__ float g_t1 [(size_t)MR * EE];
__device__ float g_h  [(size_t)MR * EE];
__device__ float g_ffa[(size_t)MR * FF];
__device__ float g_t2 [(size_t)MR * EE];
__device__ float g_kadd[MR];
__device__ float g_kneg[MR];
__device__ float g_wqkvT[(size_t)3 * EE * EE];
__device__ float g_woutT[(size_t)EE * EE];
__device__ float g_winT [(size_t)FF * EE];
__device__ float g_wffoT[(size_t)EE * FF];

// ======================= PTX helpers =======================
__device__ __forceinline__ uint32_t smem_u32(const void* p) {
    uint32_t a;
    asm("{ .reg .u64 t; cvta.to.shared.u64 t, %1; cvt.u32.u64 %0, t; }"
        : "=r"(a) : "l"(p));
    return a;
}
__device__ __forceinline__ void cp16(uint32_t dst, const void* src) {
    asm volatile("cp.async.cg.shared.global [%0], [%1], 16;" :: "r"(dst), "l"(src));
}
#define CP_COMMIT() asm volatile("cp.async.commit_group;" ::: "memory")
#define CP_WAIT0()  asm volatile("cp.async.wait_group 0;" ::: "memory")

__device__ __forceinline__ void ldsm4(uint32_t& r0, uint32_t& r1, uint32_t& r2, uint32_t& r3,
                                      uint32_t addr) {
    asm volatile("ldmatrix.sync.aligned.m8n8.x4.shared.b16 {%0,%1,%2,%3}, [%4];"
                 : "=r"(r0), "=r"(r1), "=r"(r2), "=r"(r3) : "r"(addr));
}
__device__ __forceinline__ uint32_t f2tf32(uint32_t x) {
    uint32_t y;
    asm("cvt.rna.tf32.f32 %0, %1;" : "=r"(y) : "f"(__uint_as_float(x)));
    return y;
}
__device__ __forceinline__ float rnd_tf32(float v) {
    uint32_t b;
    asm("cvt.rna.tf32.f32 %0, %1;" : "=r"(b) : "f"(v));
    return __uint_as_float(b);
}
__device__ __forceinline__ void mma_tf32(float* c, const uint32_t* a, uint32_t b0, uint32_t b1) {
    asm volatile(
        "mma.sync.aligned.m16n8k8.row.col.f32.tf32.tf32.f32 "
        "{%0,%1,%2,%3}, {%4,%5,%6,%7}, {%8,%9}, {%0,%1,%2,%3};"
        : "+f"(c[0]), "+f"(c[1]), "+f"(c[2]), "+f"(c[3])
        : "r"(a[0]), "r"(a[1]), "r"(a[2]), "r"(a[3]), "r"(b0), "r"(b1));
}

// ======================= weight transpose + tf32 round =======================
__global__ void transpose_kernel(const float* __restrict__ W, float* __restrict__ WT,
                                 int K, int N) {
    __shared__ float t[32][33];
    int n0 = blockIdx.x * 32, k0 = blockIdx.y * 32;
    int tx = threadIdx.x, ty = threadIdx.y;
#pragma unroll
    for (int i = 0; i < 32; i += 8)
        t[ty + i][tx] = W[(size_t)(k0 + ty + i) * N + n0 + tx];
    __syncthreads();
#pragma unroll
    for (int i = 0; i < 32; i += 8) {
        float v = t[tx][ty + i];
        WT[(size_t)(n0 + ty + i) * K + k0 + tx] = rnd_tf32(v);
    }
}

// ======================= mask precompute =======================
__global__ void mask_kernel(const int* __restrict__ am, const int* __restrict__ tt) {
    int i = blockIdx.x * 256 + threadIdx.x;
    if (i >= MR) return;
    bool a  = (am[i] != 0);
    bool qm = (tt[i] == 1) || (!a) || ((i & (SS - 1)) == 0);
    g_kadd[i] = a  ? 1.f : 0.f;
    g_kneg[i] = qm ? 1.f : 0.f;
}

// ======================= tf32 tensor-core GEMM v3 (kept; measured neutral) =======================
// 256 threads / 8 warps (2m x 4n), warp tile 64x64. BM=128, BN=256, BK=32, 4 stages.
#define GBM 128
#define GBN 256
#define GBK 32
#define GSTAGE_A (GBM * GBK * 4)
#define GSTAGE_B (GBN * GBK * 4)
#define GSTAGE_BYTES (GSTAGE_A + GSTAGE_B)
#define GSTAGES 4
#define GEMM_SMEM_DYN (GSTAGES * GSTAGE_BYTES)   // 192 KB

__global__ __launch_bounds__(256, 1) void mma_gemm(
    const float* __restrict__ A, const float* __restrict__ BT,
    const float* __restrict__ bias, const float* __restrict__ res,
    float* __restrict__ C, int M, int N, int K, int mode)
{
    extern __shared__ char dyn_smem[];
    uint32_t sbase = smem_u32(dyn_smem);
    int tid = threadIdx.x, lane = tid & 31, wid = tid >> 5;
    int wm = wid >> 2, wn = wid & 3;
    int bm = blockIdx.y * GBM, bn = blockIdx.x * GBN;

    float c[4][8][4];
#pragma unroll
    for (int mi = 0; mi < 4; mi++)
#pragma unroll
        for (int j = 0; j < 8; j++)
#pragma unroll
            for (int q = 0; q < 4; q++) c[mi][j][q] = 0.f;

    int T = K / GBK;

    auto load_tile = [&](int t, int s) {
        int k0 = t * GBK;
        uint32_t sA = sbase + s * GSTAGE_BYTES;
        uint32_t sB = sA + GSTAGE_A;
#pragma unroll
        for (int i = 0; i < 4; i++) {
            int g = tid + i * 256;
            int row = g >> 3, ch = g & 7;
            cp16(sA + row * 128 + ((ch ^ (row & 7)) << 4),
                 A + (size_t)(bm + row) * K + k0 + ch * 4);
        }
#pragma unroll
        for (int i = 0; i < 8; i++) {
            int g = tid + i * 256;
            int row = g >> 3, ch = g & 7;
            cp16(sB + row * 128 + ((ch ^ (row & 7)) << 4),
                 BT + (size_t)(bn + row) * K + k0 + ch * 4);
        }
    };

    load_tile(0, 0); CP_COMMIT();
    load_tile(1, 1); CP_COMMIT();
    load_tile(2, 2); CP_COMMIT();

    for (int t = 0; t < T; t++) {
        asm volatile("cp.async.wait_group 2;" ::: "memory");
        __syncthreads();
        if (t + 3 < T) load_tile(t + 3, (t + 3) & 3);
        CP_COMMIT();

        int s = t & 3;
        uint32_t sA = sbase + s * GSTAGE_BYTES;
        uint32_t sB = sA + GSTAGE_A;

#pragma unroll
        for (int p = 0; p < 2; p++) {
            uint32_t a[4][2][4];
#pragma unroll
            for (int mi = 0; mi < 4; mi++)
#pragma unroll
                for (int kk = 0; kk < 2; kk++) {
                    int ks = p * 2 + kk;
                    int r = wm * 64 + mi * 16 + ((lane >> 3) & 1) * 8 + (lane & 7);
                    int ch = ks * 2 + (lane >> 4);
                    ldsm4(a[mi][kk][0], a[mi][kk][1], a[mi][kk][2], a[mi][kk][3],
                          sA + r * 128 + ((ch ^ (r & 7)) << 4));
#pragma unroll
                    for (int q = 0; q < 4; q++) a[mi][kk][q] = f2tf32(a[mi][kk][q]);
                }
#pragma unroll
            for (int j = 0; j < 8; j++) {
                uint32_t b0, b1, b2, b3;
                int r = wn * 64 + j * 8 + (lane & 7);
                int ch = p * 4 + (lane >> 3);
                ldsm4(b0, b1, b2, b3, sB + r * 128 + ((ch ^ (r & 7)) << 4));
#pragma unroll
                for (int mi = 0; mi < 4; mi++) {
                    mma_tf32(c[mi][j], a[mi][0], b0, b1);
                    mma_tf32(c[mi][j], a[mi][1], b2, b3);
                }
            }
        }
    }

    // ---- epilogue ----
#pragma unroll
    for (int mi = 0; mi < 4; mi++) {
        int r0 = bm + wm * 64 + mi * 16 + (lane >> 2);
#pragma unroll
        for (int half = 0; half < 2; half++) {
            int r = r0 + half * 8;
            float* Crow = C + (size_t)r * N;
            const float* Rrow = res ? res + (size_t)r * N : nullptr;
#pragma unroll
            for (int j = 0; j < 8; j++) {
                int col = bn + wn * 64 + j * 8 + (lane & 3) * 2;
                float v0 = c[mi][j][half * 2 + 0] + bias[col];
                float v1 = c[mi][j][half * 2 + 1] + bias[col + 1];
                if (Rrow) { v0 += Rrow[col]; v1 += Rrow[col + 1]; }
                if (mode & 1) {
                    v0 = 0.5f * v0 * (1.0f + erff(v0 * 0.70710678118654752f));
                    v1 = 0.5f * v1 * (1.0f + erff(v1 * 0.70710678118654752f));
                }
                if (mode & 2) { v0 = rnd_tf32(v0); v1 = rnd_tf32(v1); }
                *(float2*)(Crow + col) = make_float2(v0, v1);
            }
        }
    }
}

// ======================= Pipelined flash attention (R10 version, restored) =======================
// 256 thr / 8 warps, 2 CTAs/SM (16 warps/SM), warp M=16, regs capped at 128.
#define AQ 128
#define AK 64
#define APITCH 68
#define AROW (APITCH * 4)          // 272 B row pitch
#define ATTN_SMEM_DYN ((AQ * APITCH + 4 * AK * APITCH) * 4)

__global__ __launch_bounds__(256, 2) void attn_mma(
    const float* __restrict__ QKV, float* __restrict__ CTX)
{
    extern __shared__ float as[];
    float* sQ = as;                                // 128 x 68
    float* sK0 = sQ + AQ * APITCH;                 // stage 0 K
    float* sK1 = sK0 + AK * APITCH;                // stage 1 K
    float* sV0 = sK1 + AK * APITCH;                // stage 0 VT
    float* sV1 = sV0 + AK * APITCH;                // stage 1 VT
    __shared__ float sAdd[2][AK], sNeg[2][AK];

    uint32_t uQ = smem_u32(sQ);
    uint32_t uK[2] = { smem_u32(sK0), smem_u32(sK1) };
    uint32_t uV[2] = { smem_u32(sV0), smem_u32(sV1) };
    uint32_t uA[2] = { smem_u32(&sAdd[0][0]), smem_u32(&sAdd[1][0]) };
    uint32_t uN[2] = { smem_u32(&sNeg[0][0]), smem_u32(&sNeg[1][0]) };
    float* sVT[2] = { sV0, sV1 };

    int tid = threadIdx.x, lane = tid & 31, wid = tid >> 5;
    int b = blockIdx.z, h = blockIdx.y, q0 = blockIdx.x * AQ;
    int wq0 = wid * 16;

    const float* Qb = QKV + (size_t)b * SS * 3072 + h * 64;
    const float* Kb = Qb + 1024;
    const float* Vb = Qb + 2048;
    const float* madd = g_kadd + b * SS;
    const float* mneg = g_kneg + b * SS;

    int lr = lane >> 2, sub = lane & 3;
    uint32_t qbase = lane & ~3u;
    int phalf = sub >> 1, podd = sub & 1;

    // V-transpose lane mapping
    int vg = tid >> 2;
    int vcch = vg & 15;               // d chunk (4 floats)
    int vkb0 = (vg >> 4) << 2;        // key base (it adds <<4)

    // ---------------- prologue ----------------
#pragma unroll
    for (int i = 0; i < 8; i++) {
        int g = tid + i * 256, r = g >> 4, c4 = g & 15;
        cp16(uQ + r * AROW + c4 * 16, Qb + (size_t)(q0 + r) * 3072 + c4 * 4);
    }
#pragma unroll
    for (int i = 0; i < 4; i++) {
        int g = tid + i * 256, r = g >> 4, c4 = g & 15;
        cp16(uK[0] + r * AROW + c4 * 16, Kb + (size_t)r * 3072 + c4 * 4);
    }
    if (tid < 16) cp16(uA[0] + tid * 16, madd + tid * 4);
    else if (tid < 32) cp16(uN[0] + (tid - 16) * 16, mneg + (tid - 16) * 4);
    CP_COMMIT();

    float4 pv[4];
#pragma unroll
    for (int it = 0; it < 4; it++) {
        int kb = vkb0 + (it << 4);
        pv[it] = *(const float4*)(Vb + (size_t)(kb + sub) * 3072 + vcch * 4);
    }

    float amq0 = madd[q0 + wq0 + lr];
    float amq1 = madd[q0 + wq0 + lr + 8];

    CP_WAIT0();
    __syncthreads();

    // build VT stage 0
#pragma unroll
    for (int it = 0; it < 4; it++) {
        float a0 = pv[it].x, a1 = pv[it].y, a2 = pv[it].z, a3 = pv[it].w;
        float t0, t1, t2, t3;
#pragma unroll
        for (int j = 0; j < 4; j++) {
            int sidx = (sub + j) & 3;
            float sval = sidx == 0 ? a0 : sidx == 1 ? a1 : sidx == 2 ? a2 : a3;
            int i = (sub - j) & 3;
            float r = __shfl_sync(0xffffffffu, sval, qbase | i);
            if (i == 0) t0 = r; else if (i == 1) t1 = r; else if (i == 2) t2 = r; else t3 = r;
        }
        int d = vcch * 4 + sub;
        int kb = vkb0 + (it << 4);
        *(float4*)(sVT[0] + d * APITCH + kb) = make_float4(t0, t1, t2, t3);
    }
    __syncthreads();

    // ---------------- mainloop ----------------
    float m0 = -INFINITY, m1 = -INFINITY, l0 = 0.f, l1 = 0.f;
    float o[8][4];
#pragma unroll
    for (int j = 0; j < 8; j++)
#pragma unroll
        for (int q = 0; q < 4; q++) o[j][q] = 0.f;

    const int T = SS / AK;
#pragma unroll 1
    for (int t = 0; t < T; t++) {
        int st = t & 1, sn = st ^ 1;
        bool has_next = (t + 1) < T;
        int k0n = has_next ? (t + 1) * AK : 0;

        if (has_next) {
#pragma unroll
            for (int i = 0; i < 4; i++) {
                int g = tid + i * 256, r = g >> 4, c4 = g & 15;
                cp16(uK[sn] + r * AROW + c4 * 16, Kb + (size_t)(k0n + r) * 3072 + c4 * 4);
            }
            if (tid < 16) cp16(uA[sn] + tid * 16, madd + k0n + tid * 4);
            else if (tid < 32) cp16(uN[sn] + (tid - 16) * 16, mneg + k0n + (tid - 16) * 4);
        }
        CP_COMMIT();
        if (has_next) {
#pragma unroll
            for (int it = 0; it < 4; it++) {
                int kb = vkb0 + (it << 4);
                pv[it] = *(const float4*)(Vb + (size_t)(k0n + kb + sub) * 3072 + vcch * 4);
            }
        }

        // ===== S = Q @ K^T =====
        float c[8][4];
#pragma unroll
        for (int j = 0; j < 8; j++)
#pragma unroll
            for (int q = 0; q < 4; q++) c[j][q] = 0.f;

#pragma unroll
        for (int p = 0; p < 4; p++) {
            uint32_t a[2][4];
#pragma unroll
            for (int kk = 0; kk < 2; kk++) {
                int ks = p * 2 + kk;
                int r = wq0 + ((lane >> 3) & 1) * 8 + (lane & 7);
                int ch = ks * 2 + (lane >> 4);
                ldsm4(a[kk][0], a[kk][1], a[kk][2], a[kk][3], uQ + r * AROW + ch * 16);
            }
#pragma unroll
            for (int j = 0; j < 8; j++) {
                uint32_t b0, b1, b2, b3;
                int r = j * 8 + (lane & 7);
                int ch = p * 4 + (lane >> 3);
                ldsm4(b0, b1, b2, b3, uK[st] + r * AROW + ch * 16);
                mma_tf32(c[j], a[0], b0, b1);
                mma_tf32(c[j], a[1], b2, b3);
            }
        }

        // ===== mask + online softmax =====
        float mt0 = -INFINITY, mt1 = -INFINITY;
#pragma unroll
        for (int j = 0; j < 8; j++) {
            int col = j * 8 + sub * 2;
            float ka0 = sAdd[st][col], ka1 = sAdd[st][col + 1];
            float kn0 = sNeg[st][col], kn1 = sNeg[st][col + 1];
            c[j][0] = (kn0 != 0.f) ? -1e30f : c[j][0] * 0.125f + amq0 * ka0;
            c[j][1] = (kn1 != 0.f) ? -1e30f : c[j][1] * 0.125f + amq0 * ka1;
            c[j][2] = (kn0 != 0.f) ? -1e30f : c[j][2] * 0.125f + amq1 * ka0;
            c[j][3] = (kn1 != 0.f) ? -1e30f : c[j][3] * 0.125f + amq1 * ka1;
            mt0 = fmaxf(mt0, fmaxf(c[j][0], c[j][1]));
            mt1 = fmaxf(mt1, fmaxf(c[j][2], c[j][3]));
        }
        mt0 = fmaxf(mt0, __shfl_xor_sync(0xffffffffu, mt0, 1));
        mt0 = fmaxf(mt0, __shfl_xor_sync(0xffffffffu, mt0, 2));
        mt1 = fmaxf(mt1, __shfl_xor_sync(0xffffffffu, mt1, 1));
        mt1 = fmaxf(mt1, __shfl_xor_sync(0xffffffffu, mt1, 2));

        float mn0 = fmaxf(m0, mt0), mn1 = fmaxf(m1, mt1);
        float alpha0 = __expf(m0 - mn0), alpha1 = __expf(m1 - mn1);
        m0 = mn0; m1 = mn1;

        float s0 = 0.f, s1 = 0.f;
#pragma unroll
        for (int j = 0; j < 8; j++) {
            c[j][0] = __expf(c[j][0] - mn0);
            c[j][1] = __expf(c[j][1] - mn0);
            c[j][2] = __expf(c[j][2] - mn1);
            c[j][3] = __expf(c[j][3] - mn1);
            s0 += c[j][0] + c[j][1];
            s1 += c[j][2] + c[j][3];
        }
        s0 += __shfl_xor_sync(0xffffffffu, s0, 1);
        s0 += __shfl_xor_sync(0xffffffffu, s0, 2);
        s1 += __shfl_xor_sync(0xffffffffu, s1, 1);
        s1 += __shfl_xor_sync(0xffffffffu, s1, 2);
        l0 = l0 * alpha0 + s0;
        l1 = l1 * alpha1 + s1;

#pragma unroll
        for (int j = 0; j < 8; j++) {
            o[j][0] *= alpha0; o[j][1] *= alpha0;
            o[j][2] *= alpha1; o[j][3] *= alpha1;
        }

        // ===== O += P @ V : P frags via intra-quad shfl =====
#pragma unroll
        for (int p = 0; p < 4; p++) {
            uint32_t a_lo[4], a_hi[4];
#pragma unroll
            for (int hh = 0; hh < 2; hh++) {
                int kc = 2 * p + hh;
                float v00 = __shfl_sync(0xffffffffu, c[kc][0], qbase + phalf);
                float v01 = __shfl_sync(0xffffffffu, c[kc][1], qbase + phalf);
                float v10 = __shfl_sync(0xffffffffu, c[kc][2], qbase + phalf);
                float v11 = __shfl_sync(0xffffffffu, c[kc][3], qbase + phalf);
                float v20 = __shfl_sync(0xffffffffu, c[kc][0], qbase + 2 + phalf);
                float v21 = __shfl_sync(0xffffffffu, c[kc][1], qbase + 2 + phalf);
                float v30 = __shfl_sync(0xffffffffu, c[kc][2], qbase + 2 + phalf);
                float v31 = __shfl_sync(0xffffffffu, c[kc][3], qbase + 2 + phalf);
                uint32_t* a = hh ? a_hi : a_lo;
                a[0] = __float_as_uint(podd ? v01 : v00);
                a[1] = __float_as_uint(podd ? v11 : v10);
                a[2] = __float_as_uint(podd ? v21 : v20);
                a[3] = __float_as_uint(podd ? v31 : v30);
            }
#pragma unroll
            for (int j = 0; j < 8; j++) {
                uint32_t b0, b1, b2, b3;
                int r = j * 8 + (lane & 7);
                int ch = p * 4 + (lane >> 3);
                ldsm4(b0, b1, b2, b3, uV[st] + r * AROW + ch * 16);
                mma_tf32(o[j], a_lo, b0, b1);
                mma_tf32(o[j], a_hi, b2, b3);
            }
        }

        // ===== build VT[t+1] =====
        if (has_next) {
#pragma unroll
            for (int it = 0; it < 4; it++) {
                float a0 = pv[it].x, a1 = pv[it].y, a2 = pv[it].z, a3 = pv[it].w;
                float t0, t1, t2, t3;
#pragma unroll
                for (int j = 0; j < 4; j++) {
                    int sidx = (sub + j) & 3;
                    float sval = sidx == 0 ? a0 : sidx == 1 ? a1 : sidx == 2 ? a2 : a3;
                    int i = (sub - j) & 3;
                    float r = __shfl_sync(0xffffffffu, sval, qbase | i);
                    if (i == 0) t0 = r; else if (i == 1) t1 = r; else if (i == 2) t2 = r; else t3 = r;
                }
                int d = vcch * 4 + sub;
                int kb = vkb0 + (it << 4);
                *(float4*)(sVT[sn] + d * APITCH + kb) = make_float4(t0, t1, t2, t3);
            }
        }

        CP_WAIT0();
        __syncthreads();
    }

    // ---- epilogue ----
    float inv0 = 1.f / l0, inv1 = 1.f / l1;
    size_t row0 = (size_t)(b * SS + q0 + wq0 + lr);
    size_t row1 = row0 + 8;
#pragma unroll
    for (int j = 0; j < 8; j++) {
        int col = h * 64 + j * 8 + sub * 2;
        *(float2*)(CTX + row0 * EE + col) = make_float2(o[j][0] * inv0, o[j][1] * inv0);
        *(float2*)(CTX + row1 * EE + col) = make_float2(o[j][2] * inv1, o[j][3] * inv1);
    }
}

// ======================= LayerNorm =======================
__global__ __launch_bounds__(256) void ln_kernel(
    const float* __restrict__ in, const float* __restrict__ w,
    const float* __restrict__ b, float* __restrict__ out)
{
    int row = blockIdx.x;
    const float* x = in + (size_t)row * EE;
    int tid = threadIdx.x;

    float v[4], s = 0.f, sq = 0.f;
#pragma unroll
    for (int i = 0; i < 4; i++) {
        v[i] = x[tid + i * 256];
        s += v[i];
        sq += v[i] * v[i];
    }
#pragma unroll
    for (int off = 16; off > 0; off >>= 1) {
        s  += __shfl_xor_sync(0xffffffffu, s,  off);
        sq += __shfl_xor_sync(0xffffffffu, sq, off);
    }
    __shared__ float ss[8], ssq[8];
    if ((tid & 31) == 0) { ss[tid >> 5] = s; ssq[tid >> 5] = sq; }
    __syncthreads();
    float ts = 0.f, tsq = 0.f;
#pragma unroll
    for (int wi = 0; wi < 8; wi++) { ts += ss[wi]; tsq += ssq[wi]; }
    float mean = ts * (1.f / EE);
    float var = tsq * (1.f / EE) - mean * mean;
    float rstd = rsqrtf(var + 1e-12f);
    float* y = out + (size_t)row * EE;
#pragma unroll
    for (int i = 0; i < 4; i++) {
        int c = tid + i * 256;
        y[c] = (v[i] - mean) * rstd * w[c] + b[c];
    }
}

// ======================= launch =======================
extern "C" void kernel_launch(void* const* d_in, const int* in_sizes, int n_in,
                              void* d_out, int out_size)
{
    const float* x      = (const float*)d_in[0];
    const int*   am     = (const int*)d_in[1];
    const int*   tt     = (const int*)d_in[2];
    const float* w_qkv  = (const float*)d_in[3];
    const float* b_qkv  = (const float*)d_in[4];
    const float* w_out  = (const float*)d_in[5];
    const float* b_outp = (const float*)d_in[6];
    const float* ln_w   = (const float*)d_in[7];
    const float* ln_b   = (const float*)d_in[8];
    const float* w_in   = (const float*)d_in[9];
    const float* b_in   = (const float*)d_in[10];
    const float* w_ffo  = (const float*)d_in[11];
    const float* b_ffo  = (const float*)d_in[12];
    float* out = (float*)d_out;

    float *qkv, *ctx, *t1, *hb, *ffa, *t2, *wqkvT, *woutT, *winT, *wffoT;
    cudaGetSymbolAddress((void**)&qkv,   g_qkv);
    cudaGetSymbolAddress((void**)&ctx,   g_ctx);
    cudaGetSymbolAddress((void**)&t1,    g_t1);
    cudaGetSymbolAddress((void**)&hb,    g_h);
    cudaGetSymbolAddress((void**)&ffa,   g_ffa);
    cudaGetSymbolAddress((void**)&t2,    g_t2);
    cudaGetSymbolAddress((void**)&wqkvT, g_wqkvT);
    cudaGetSymbolAddress((void**)&woutT, g_woutT);
    cudaGetSymbolAddress((void**)&winT,  g_winT);
    cudaGetSymbolAddress((void**)&wffoT, g_wffoT);

    cudaFuncSetAttribute(attn_mma, cudaFuncAttributeMaxDynamicSharedMemorySize, ATTN_SMEM_DYN);
    cudaFuncSetAttribute(mma_gemm, cudaFuncAttributeMaxDynamicSharedMemorySize, GEMM_SMEM_DYN);

    dim3 tb(32, 8);
    transpose_kernel<<<dim3(3 * EE / 32, EE / 32), tb>>>(w_qkv, wqkvT, EE, 3 * EE);
    mask_kernel<<<MR / 256, 256>>>(am, tt);

    // QKV projection -> output rounded to tf32 (mode=2)
    mma_gemm<<<dim3(3 * EE / GBN, MR / GBM), 256, GEMM_SMEM_DYN>>>(
        x, wqkvT, b_qkv, nullptr, qkv, MR, 3 * EE, EE, 2);
    // attention (R10 pipelined tensor-core flash)
    attn_mma<<<dim3(SS / AQ, HH, BB), 256, ATTN_SMEM_DYN>>>(qkv, ctx);

    transpose_kernel<<<dim3(EE / 32, EE / 32), tb>>>(w_out, woutT, EE, EE);
    // out projection + residual
    mma_gemm<<<dim3(EE / GBN, MR / GBM), 256, GEMM_SMEM_DYN>>>(
        ctx, woutT, b_outp, x, t1, MR, EE, EE, 0);
    // LN -> h
    ln_kernel<<<MR, 256>>>(t1, ln_w, ln_b, hb);

    transpose_kernel<<<dim3(FF / 32, EE / 32), tb>>>(w_in,  winT,  EE, FF);
    // FFN in + GELU
    mma_gemm<<<dim3(FF / GBN, MR / GBM), 256, GEMM_SMEM_DYN>>>(
        hb, winT, b_in, nullptr, ffa, MR, FF, EE, 1);

    transpose_kernel<<<dim3(EE / 32, FF / 32), tb>>>(w_ffo, wffoT, FF, EE);
    // FFN out + residual
    mma_gemm<<<dim3(EE / GBN, MR / GBM), 256, GEMM_SMEM_DYN>>>(
        ffa, wffoT, b_ffo, hb, t2, MR, EE, FF, 0);
    // LN -> out
    ln_kernel<<<MR, 256>>>(t2, ln_w, ln_b, out);
}

// round 16
// speedup vs baseline: 1.1531x; 1.0280x over previous
#include <cuda_runtime.h>
#include <math.h>
#include <stdint.h>

// Problem constants
#define BB   8
#define SS   1024
#define EE   1024
#define HH   16
#define FF   4096
#define MR   (BB*SS)      // 8192 rows

// -------- scratch (static device globals; no runtime allocation) --------
__device__ float g_qkv[(size_t)MR * 3 * EE];
__device__ float g_ctx[(size_t)MR * EE];
__device__ float g_t1 [(size_t)MR * EE];
__device__ float g_h  [(size_t)MR * EE];
__device__ float g_hr [(size_t)MR * EE];      // tf32-rounded copy of h (GEMM A input)
__device__ float g_xr [(size_t)MR * EE];      // tf32-rounded copy of x (GEMM A input)
__device__ float g_ffa[(size_t)MR * FF];
__device__ float g_t2 [(size_t)MR * EE];
__device__ float g_kadd[MR];
__device__ float g_kneg[MR];
__device__ float g_wqkvT[(size_t)3 * EE * EE];
__device__ float g_woutT[(size_t)EE * EE];
__device__ float g_winT [(size_t)FF * EE];
__device__ float g_wffoT[(size_t)EE * FF];

// ======================= PTX helpers =======================
__device__ __forceinline__ uint32_t smem_u32(const void* p) {
    uint32_t a;
    asm("{ .reg .u64 t; cvta.to.shared.u64 t, %1; cvt.u32.u64 %0, t; }"
        : "=r"(a) : "l"(p));
    return a;
}
__device__ __forceinline__ void cp16(uint32_t dst, const void* src) {
    asm volatile("cp.async.cg.shared.global [%0], [%1], 16;" :: "r"(dst), "l"(src));
}
#define CP_COMMIT() asm volatile("cp.async.commit_group;" ::: "memory")
#define CP_WAIT0()  asm volatile("cp.async.wait_group 0;" ::: "memory")

__device__ __forceinline__ void ldsm4(uint32_t& r0, uint32_t& r1, uint32_t& r2, uint32_t& r3,
                                      uint32_t addr) {
    asm volatile("ldmatrix.sync.aligned.m8n8.x4.shared.b16 {%0,%1,%2,%3}, [%4];"
                 : "=r"(r0), "=r"(r1), "=r"(r2), "=r"(r3) : "r"(addr));
}
__device__ __forceinline__ float rnd_tf32(float v) {
    uint32_t b;
    asm("cvt.rna.tf32.f32 %0, %1;" : "=r"(b) : "f"(v));
    return __uint_as_float(b);
}
__device__ __forceinline__ void mma_tf32(float* c, const uint32_t* a, uint32_t b0, uint32_t b1) {
    asm volatile(
        "mma.sync.aligned.m16n8k8.row.col.f32.tf32.tf32.f32 "
        "{%0,%1,%2,%3}, {%4,%5,%6,%7}, {%8,%9}, {%0,%1,%2,%3};"
        : "+f"(c[0]), "+f"(c[1]), "+f"(c[2]), "+f"(c[3])
        : "r"(a[0]), "r"(a[1]), "r"(a[2]), "r"(a[3]), "r"(b0), "r"(b1));
}

// ======================= weight transpose + tf32 round =======================
__global__ void transpose_kernel(const float* __restrict__ W, float* __restrict__ WT,
                                 int K, int N) {
    __shared__ float t[32][33];
    int n0 = blockIdx.x * 32, k0 = blockIdx.y * 32;
    int tx = threadIdx.x, ty = threadIdx.y;
#pragma unroll
    for (int i = 0; i < 32; i += 8)
        t[ty + i][tx] = W[(size_t)(k0 + ty + i) * N + n0 + tx];
    __syncthreads();
#pragma unroll
    for (int i = 0; i < 32; i += 8) {
        float v = t[tx][ty + i];
        WT[(size_t)(n0 + ty + i) * K + k0 + tx] = rnd_tf32(v);
    }
}

// ======================= elementwise tf32 round (x -> xr) =======================
__global__ void round_kernel(const float* __restrict__ in, float* __restrict__ out, int n4) {
    int i = blockIdx.x * 256 + threadIdx.x;
    if (i >= n4) return;
    float4 v = ((const float4*)in)[i];
    v.x = rnd_tf32(v.x); v.y = rnd_tf32(v.y); v.z = rnd_tf32(v.z); v.w = rnd_tf32(v.w);
    ((float4*)out)[i] = v;
}

// ======================= mask precompute =======================
__global__ void mask_kernel(const int* __restrict__ am, const int* __restrict__ tt) {
    int i = blockIdx.x * 256 + threadIdx.x;
    if (i >= MR) return;
    bool a  = (am[i] != 0);
    bool qm = (tt[i] == 1) || (!a) || ((i & (SS - 1)) == 0);
    g_kadd[i] = a  ? 1.f : 0.f;
    g_kneg[i] = qm ? 1.f : 0.f;
}

// ======================= tf32 tensor-core GEMM v4 (cvt-free mainloop) =======================
// A inputs MUST be pre-rounded to tf32. 256 thr / 8 warps (2m x 4n), warp tile 64x64.
// mode: bit0 = exact GELU; bit1 = round output to tf32
#define GBM 128
#define GBN 256
#define GBK 32
#define GSTAGE_A (GBM * GBK * 4)
#define GSTAGE_B (GBN * GBK * 4)
#define GSTAGE_BYTES (GSTAGE_A + GSTAGE_B)
#define GSTAGES 4
#define GEMM_SMEM_DYN (GSTAGES * GSTAGE_BYTES)   // 192 KB

__global__ __launch_bounds__(256, 1) void mma_gemm(
    const float* __restrict__ A, const float* __restrict__ BT,
    const float* __restrict__ bias, const float* __restrict__ res,
    float* __restrict__ C, int M, int N, int K, int mode)
{
    extern __shared__ char dyn_smem[];
    uint32_t sbase = smem_u32(dyn_smem);
    int tid = threadIdx.x, lane = tid & 31, wid = tid >> 5;
    int wm = wid >> 2, wn = wid & 3;
    int bm = blockIdx.y * GBM, bn = blockIdx.x * GBN;

    float c[4][8][4];
#pragma unroll
    for (int mi = 0; mi < 4; mi++)
#pragma unroll
        for (int j = 0; j < 8; j++)
#pragma unroll
            for (int q = 0; q < 4; q++) c[mi][j][q] = 0.f;

    int T = K / GBK;

    auto load_tile = [&](int t, int s) {
        int k0 = t * GBK;
        uint32_t sA = sbase + s * GSTAGE_BYTES;
        uint32_t sB = sA + GSTAGE_A;
#pragma unroll
        for (int i = 0; i < 4; i++) {
            int g = tid + i * 256;
            int row = g >> 3, ch = g & 7;
            cp16(sA + row * 128 + ((ch ^ (row & 7)) << 4),
                 A + (size_t)(bm + row) * K + k0 + ch * 4);
        }
#pragma unroll
        for (int i = 0; i < 8; i++) {
            int g = tid + i * 256;
            int row = g >> 3, ch = g & 7;
            cp16(sB + row * 128 + ((ch ^ (row & 7)) << 4),
                 BT + (size_t)(bn + row) * K + k0 + ch * 4);
        }
    };

    load_tile(0, 0); CP_COMMIT();
    load_tile(1, 1); CP_COMMIT();
    load_tile(2, 2); CP_COMMIT();

    for (int t = 0; t < T; t++) {
        asm volatile("cp.async.wait_group 2;" ::: "memory");
        __syncthreads();
        if (t + 3 < T) load_tile(t + 3, (t + 3) & 3);
        CP_COMMIT();

        int s = t & 3;
        uint32_t sA = sbase + s * GSTAGE_BYTES;
        uint32_t sB = sA + GSTAGE_A;

#pragma unroll
        for (int p = 0; p < 2; p++) {
            uint32_t a[4][2][4];
#pragma unroll
            for (int mi = 0; mi < 4; mi++)
#pragma unroll
                for (int kk = 0; kk < 2; kk++) {
                    int ks = p * 2 + kk;
                    int r = wm * 64 + mi * 16 + ((lane >> 3) & 1) * 8 + (lane & 7);
                    int ch = ks * 2 + (lane >> 4);
                    ldsm4(a[mi][kk][0], a[mi][kk][1], a[mi][kk][2], a[mi][kk][3],
                          sA + r * 128 + ((ch ^ (r & 7)) << 4));
                }
#pragma unroll
            for (int j = 0; j < 8; j++) {
                uint32_t b0, b1, b2, b3;
                int r = wn * 64 + j * 8 + (lane & 7);
                int ch = p * 4 + (lane >> 3);
                ldsm4(b0, b1, b2, b3, sB + r * 128 + ((ch ^ (r & 7)) << 4));
#pragma unroll
                for (int mi = 0; mi < 4; mi++) {
                    mma_tf32(c[mi][j], a[mi][0], b0, b1);
                    mma_tf32(c[mi][j], a[mi][1], b2, b3);
                }
            }
        }
    }

    // ---- epilogue ----
#pragma unroll
    for (int mi = 0; mi < 4; mi++) {
        int r0 = bm + wm * 64 + mi * 16 + (lane >> 2);
#pragma unroll
        for (int half = 0; half < 2; half++) {
            int r = r0 + half * 8;
            float* Crow = C + (size_t)r * N;
            const float* Rrow = res ? res + (size_t)r * N : nullptr;
#pragma unroll
            for (int j = 0; j < 8; j++) {
                int col = bn + wn * 64 + j * 8 + (lane & 3) * 2;
                float v0 = c[mi][j][half * 2 + 0] + bias[col];
                float v1 = c[mi][j][half * 2 + 1] + bias[col + 1];
                if (Rrow) { v0 += Rrow[col]; v1 += Rrow[col + 1]; }
                if (mode & 1) {
                    v0 = 0.5f * v0 * (1.0f + erff(v0 * 0.70710678118654752f));
                    v1 = 0.5f * v1 * (1.0f + erff(v1 * 0.70710678118654752f));
                }
                if (mode & 2) { v0 = rnd_tf32(v0); v1 = rnd_tf32(v1); }
                *(float2*)(Crow + col) = make_float2(v0, v1);
            }
        }
    }
}

// ======================= Pipelined flash attention (R10/R15; ctx rounded on store) ==========
#define AQ 128
#define AK 64
#define APITCH 68
#define AROW (APITCH * 4)
#define ATTN_SMEM_DYN ((AQ * APITCH + 4 * AK * APITCH) * 4)

__global__ __launch_bounds__(256, 2) void attn_mma(
    const float* __restrict__ QKV, float* __restrict__ CTX)
{
    extern __shared__ float as[];
    float* sQ = as;
    float* sK0 = sQ + AQ * APITCH;
    float* sK1 = sK0 + AK * APITCH;
    float* sV0 = sK1 + AK * APITCH;
    float* sV1 = sV0 + AK * APITCH;
    __shared__ float sAdd[2][AK], sNeg[2][AK];

    uint32_t uQ = smem_u32(sQ);
    uint32_t uK[2] = { smem_u32(sK0), smem_u32(sK1) };
    uint32_t uV[2] = { smem_u32(sV0), smem_u32(sV1) };
    uint32_t uA[2] = { smem_u32(&sAdd[0][0]), smem_u32(&sAdd[1][0]) };
    uint32_t uN[2] = { smem_u32(&sNeg[0][0]), smem_u32(&sNeg[1][0]) };
    float* sVT[2] = { sV0, sV1 };

    int tid = threadIdx.x, lane = tid & 31, wid = tid >> 5;
    int b = blockIdx.z, h = blockIdx.y, q0 = blockIdx.x * AQ;
    int wq0 = wid * 16;

    const float* Qb = QKV + (size_t)b * SS * 3072 + h * 64;
    const float* Kb = Qb + 1024;
    const float* Vb = Qb + 2048;
    const float* madd = g_kadd + b * SS;
    const float* mneg = g_kneg + b * SS;

    int lr = lane >> 2, sub = lane & 3;
    uint32_t qbase = lane & ~3u;
    int phalf = sub >> 1, podd = sub & 1;

    int vg = tid >> 2;
    int vcch = vg & 15;
    int vkb0 = (vg >> 4) << 2;

    // ---------------- prologue ----------------
#pragma unroll
    for (int i = 0; i < 8; i++) {
        int g = tid + i * 256, r = g >> 4, c4 = g & 15;
        cp16(uQ + r * AROW + c4 * 16, Qb + (size_t)(q0 + r) * 3072 + c4 * 4);
    }
#pragma unroll
    for (int i = 0; i < 4; i++) {
        int g = tid + i * 256, r = g >> 4, c4 = g & 15;
        cp16(uK[0] + r * AROW + c4 * 16, Kb + (size_t)r * 3072 + c4 * 4);
    }
    if (tid < 16) cp16(uA[0] + tid * 16, madd + tid * 4);
    else if (tid < 32) cp16(uN[0] + (tid - 16) * 16, mneg + (tid - 16) * 4);
    CP_COMMIT();

    float4 pv[4];
#pragma unroll
    for (int it = 0; it < 4; it++) {
        int kb = vkb0 + (it << 4);
        pv[it] = *(const float4*)(Vb + (size_t)(kb + sub) * 3072 + vcch * 4);
    }

    float amq0 = madd[q0 + wq0 + lr];
    float amq1 = madd[q0 + wq0 + lr + 8];

    CP_WAIT0();
    __syncthreads();

#pragma unroll
    for (int it = 0; it < 4; it++) {
        float a0 = pv[it].x, a1 = pv[it].y, a2 = pv[it].z, a3 = pv[it].w;
        float t0, t1, t2, t3;
#pragma unroll
        for (int j = 0; j < 4; j++) {
            int sidx = (sub + j) & 3;
            float sval = sidx == 0 ? a0 : sidx == 1 ? a1 : sidx == 2 ? a2 : a3;
            int i = (sub - j) & 3;
            float r = __shfl_sync(0xffffffffu, sval, qbase | i);
            if (i == 0) t0 = r; else if (i == 1) t1 = r; else if (i == 2) t2 = r; else t3 = r;
        }
        int d = vcch * 4 + sub;
        int kb = vkb0 + (it << 4);
        *(float4*)(sVT[0] + d * APITCH + kb) = make_float4(t0, t1, t2, t3);
    }
    __syncthreads();

    // ---------------- mainloop ----------------
    float m0 = -INFINITY, m1 = -INFINITY, l0 = 0.f, l1 = 0.f;
    float o[8][4];
#pragma unroll
    for (int j = 0; j < 8; j++)
#pragma unroll
        for (int q = 0; q < 4; q++) o[j][q] = 0.f;

    const int T = SS / AK;
#pragma unroll 1
    for (int t = 0; t < T; t++) {
        int st = t & 1, sn = st ^ 1;
        bool has_next = (t + 1) < T;
        int k0n = has_next ? (t + 1) * AK : 0;

        if (has_next) {
#pragma unroll
            for (int i = 0; i < 4; i++) {
                int g = tid + i * 256, r = g >> 4, c4 = g & 15;
                cp16(uK[sn] + r * AROW + c4 * 16, Kb + (size_t)(k0n + r) * 3072 + c4 * 4);
            }
            if (tid < 16) cp16(uA[sn] + tid * 16, madd + k0n + tid * 4);
            else if (tid < 32) cp16(uN[sn] + (tid - 16) * 16, mneg + k0n + (tid - 16) * 4);
        }
        CP_COMMIT();
        if (has_next) {
#pragma unroll
            for (int it = 0; it < 4; it++) {
                int kb = vkb0 + (it << 4);
                pv[it] = *(const float4*)(Vb + (size_t)(k0n + kb + sub) * 3072 + vcch * 4);
            }
        }

        // ===== S = Q @ K^T =====
        float c[8][4];
#pragma unroll
        for (int j = 0; j < 8; j++)
#pragma unroll
            for (int q = 0; q < 4; q++) c[j][q] = 0.f;

#pragma unroll
        for (int p = 0; p < 4; p++) {
            uint32_t a[2][4];
#pragma unroll
            for (int kk = 0; kk < 2; kk++) {
                int ks = p * 2 + kk;
                int r = wq0 + ((lane >> 3) & 1) * 8 + (lane & 7);
                int ch = ks * 2 + (lane >> 4);
                ldsm4(a[kk][0], a[kk][1], a[kk][2], a[kk][3], uQ + r * AROW + ch * 16);
            }
#pragma unroll
            for (int j = 0; j < 8; j++) {
                uint32_t b0, b1, b2, b3;
                int r = j * 8 + (lane & 7);
                int ch = p * 4 + (lane >> 3);
                ldsm4(b0, b1, b2, b3, uK[st] + r * AROW + ch * 16);
                mma_tf32(c[j], a[0], b0, b1);
                mma_tf32(c[j], a[1], b2, b3);
            }
        }

        // ===== mask + online softmax =====
        float mt0 = -INFINITY, mt1 = -INFINITY;
#pragma unroll
        for (int j = 0; j < 8; j++) {
            int col = j * 8 + sub * 2;
            float ka0 = sAdd[st][col], ka1 = sAdd[st][col + 1];
            float kn0 = sNeg[st][col], kn1 = sNeg[st][col + 1];
            c[j][0] = (kn0 != 0.f) ? -1e30f : c[j][0] * 0.125f + amq0 * ka0;
            c[j][1] = (kn1 != 0.f) ? -1e30f : c[j][1] * 0.125f + amq0 * ka1;
            c[j][2] = (kn0 != 0.f) ? -1e30f : c[j][2] * 0.125f + amq1 * ka0;
            c[j][3] = (kn1 != 0.f) ? -1e30f : c[j][3] * 0.125f + amq1 * ka1;
            mt0 = fmaxf(mt0, fmaxf(c[j][0], c[j][1]));
            mt1 = fmaxf(mt1, fmaxf(c[j][2], c[j][3]));
        }
        mt0 = fmaxf(mt0, __shfl_xor_sync(0xffffffffu, mt0, 1));
        mt0 = fmaxf(mt0, __shfl_xor_sync(0xffffffffu, mt0, 2));
        mt1 = fmaxf(mt1, __shfl_xor_sync(0xffffffffu, mt1, 1));
        mt1 = fmaxf(mt1, __shfl_xor_sync(0xffffffffu, mt1, 2));

        float mn0 = fmaxf(m0, mt0), mn1 = fmaxf(m1, mt1);
        float alpha0 = __expf(m0 - mn0), alpha1 = __expf(m1 - mn1);
        m0 = mn0; m1 = mn1;

        float s0 = 0.f, s1 = 0.f;
#pragma unroll
        for (int j = 0; j < 8; j++) {
            c[j][0] = __expf(c[j][0] - mn0);
            c[j][1] = __expf(c[j][1] - mn0);
            c[j][2] = __expf(c[j][2] - mn1);
            c[j][3] = __expf(c[j][3] - mn1);
            s0 += c[j][0] + c[j][1];
            s1 += c[j][2] + c[j][3];
        }
        s0 += __shfl_xor_sync(0xffffffffu, s0, 1);
        s0 += __shfl_xor_sync(0xffffffffu, s0, 2);
        s1 += __shfl_xor_sync(0xffffffffu, s1, 1);
        s1 += __shfl_xor_sync(0xffffffffu, s1, 2);
        l0 = l0 * alpha0 + s0;
        l1 = l1 * alpha1 + s1;

#pragma unroll
        for (int j = 0; j < 8; j++) {
            o[j][0] *= alpha0; o[j][1] *= alpha0;
            o[j][2] *= alpha1; o[j][3] *= alpha1;
        }

        // ===== O += P @ V =====
#pragma unroll
        for (int p = 0; p < 4; p++) {
            uint32_t a_lo[4], a_hi[4];
#pragma unroll
            for (int hh = 0; hh < 2; hh++) {
                int kc = 2 * p + hh;
                float v00 = __shfl_sync(0xffffffffu, c[kc][0], qbase + phalf);
                float v01 = __shfl_sync(0xffffffffu, c[kc][1], qbase + phalf);
                float v10 = __shfl_sync(0xffffffffu, c[kc][2], qbase + phalf);
                float v11 = __shfl_sync(0xffffffffu, c[kc][3], qbase + phalf);
                float v20 = __shfl_sync(0xffffffffu, c[kc][0], qbase + 2 + phalf);
                float v21 = __shfl_sync(0xffffffffu, c[kc][1], qbase + 2 + phalf);
                float v30 = __shfl_sync(0xffffffffu, c[kc][2], qbase + 2 + phalf);
                float v31 = __shfl_sync(0xffffffffu, c[kc][3], qbase + 2 + phalf);
                uint32_t* a = hh ? a_hi : a_lo;
                a[0] = __float_as_uint(podd ? v01 : v00);
                a[1] = __float_as_uint(podd ? v11 : v10);
                a[2] = __float_as_uint(podd ? v21 : v20);
                a[3] = __float_as_uint(podd ? v31 : v30);
            }
#pragma unroll
            for (int j = 0; j < 8; j++) {
                uint32_t b0, b1, b2, b3;
                int r = j * 8 + (lane & 7);
                int ch = p * 4 + (lane >> 3);
                ldsm4(b0, b1, b2, b3, uV[st] + r * AROW + ch * 16);
                mma_tf32(o[j], a_lo, b0, b1);
                mma_tf32(o[j], a_hi, b2, b3);
            }
        }

        // ===== build VT[t+1] =====
        if (has_next) {
#pragma unroll
            for (int it = 0; it < 4; it++) {
                float a0 = pv[it].x, a1 = pv[it].y, a2 = pv[it].z, a3 = pv[it].w;
                float t0, t1, t2, t3;
#pragma unroll
                for (int j = 0; j < 4; j++) {
                    int sidx = (sub + j) & 3;
                    float sval = sidx == 0 ? a0 : sidx == 1 ? a1 : sidx == 2 ? a2 : a3;
                    int i = (sub - j) & 3;
                    float r = __shfl_sync(0xffffffffu, sval, qbase | i);
                    if (i == 0) t0 = r; else if (i == 1) t1 = r; else if (i == 2) t2 = r; else t3 = r;
                }
                int d = vcch * 4 + sub;
                int kb = vkb0 + (it << 4);
                *(float4*)(sVT[sn] + d * APITCH + kb) = make_float4(t0, t1, t2, t3);
            }
        }

        CP_WAIT0();
        __syncthreads();
    }

    // ---- epilogue: normalize + ROUND TO TF32 (ctx only feeds the out-proj GEMM) ----
    float inv0 = 1.f / l0, inv1 = 1.f / l1;
    size_t row0 = (size_t)(b * SS + q0 + wq0 + lr);
    size_t row1 = row0 + 8;
#pragma unroll
    for (int j = 0; j < 8; j++) {
        int col = h * 64 + j * 8 + sub * 2;
        *(float2*)(CTX + row0 * EE + col) =
            make_float2(rnd_tf32(o[j][0] * inv0), rnd_tf32(o[j][1] * inv0));
        *(float2*)(CTX + row1 * EE + col) =
            make_float2(rnd_tf32(o[j][2] * inv1), rnd_tf32(o[j][3] * inv1));
    }
}

// ======================= LayerNorm (optional second rounded output) =======================
__global__ __launch_bounds__(256) void ln_kernel(
    const float* __restrict__ in, const float* __restrict__ w,
    const float* __restrict__ b, float* __restrict__ out,
    float* __restrict__ out_rounded)
{
    int row = blockIdx.x;
    const float* x = in + (size_t)row * EE;
    int tid = threadIdx.x;

    float v[4], s = 0.f, sq = 0.f;
#pragma unroll
    for (int i = 0; i < 4; i++) {
        v[i] = x[tid + i * 256];
        s += v[i];
        sq += v[i] * v[i];
    }
#pragma unroll
    for (int off = 16; off > 0; off >>= 1) {
        s  += __shfl_xor_sync(0xffffffffu, s,  off);
        sq += __shfl_xor_sync(0xffffffffu, sq, off);
    }
    __shared__ float ss[8], ssq[8];
    if ((tid & 31) == 0) { ss[tid >> 5] = s; ssq[tid >> 5] = sq; }
    __syncthreads();
    float ts = 0.f, tsq = 0.f;
#pragma unroll
    for (int wi = 0; wi < 8; wi++) { ts += ss[wi]; tsq += ssq[wi]; }
    float mean = ts * (1.f / EE);
    float var = tsq * (1.f / EE) - mean * mean;
    float rstd = rsqrtf(var + 1e-12f);
    float* y = out + (size_t)row * EE;
    float* yr = out_rounded ? out_rounded + (size_t)row * EE : nullptr;
#pragma unroll
    for (int i = 0; i < 4; i++) {
        int c = tid + i * 256;
        float val = (v[i] - mean) * rstd * w[c] + b[c];
        y[c] = val;
        if (yr) yr[c] = rnd_tf32(val);
    }
}

// ======================= launch =======================
extern "C" void kernel_launch(void* const* d_in, const int* in_sizes, int n_in,
                              void* d_out, int out_size)
{
    const float* x      = (const float*)d_in[0];
    const int*   am     = (const int*)d_in[1];
    const int*   tt     = (const int*)d_in[2];
    const float* w_qkv  = (const float*)d_in[3];
    const float* b_qkv  = (const float*)d_in[4];
    const float* w_out  = (const float*)d_in[5];
    const float* b_outp = (const float*)d_in[6];
    const float* ln_w   = (const float*)d_in[7];
    const float* ln_b   = (const float*)d_in[8];
    const float* w_in   = (const float*)d_in[9];
    const float* b_in   = (const float*)d_in[10];
    const float* w_ffo  = (const float*)d_in[11];
    const float* b_ffo  = (const float*)d_in[12];
    float* out = (float*)d_out;

    float *qkv, *ctx, *t1, *hb, *hbr, *xr, *ffa, *t2, *wqkvT, *woutT, *winT, *wffoT;
    cudaGetSymbolAddress((void**)&qkv,   g_qkv);
    cudaGetSymbolAddress((void**)&ctx,   g_ctx);
    cudaGetSymbolAddress((void**)&t1,    g_t1);
    cudaGetSymbolAddress((void**)&hb,    g_h);
    cudaGetSymbolAddress((void**)&hbr,   g_hr);
    cudaGetSymbolAddress((void**)&xr,    g_xr);
    cudaGetSymbolAddress((void**)&ffa,   g_ffa);
    cudaGetSymbolAddress((void**)&t2,    g_t2);
    cudaGetSymbolAddress((void**)&wqkvT, g_wqkvT);
    cudaGetSymbolAddress((void**)&woutT, g_woutT);
    cudaGetSymbolAddress((void**)&winT,  g_winT);
    cudaGetSymbolAddress((void**)&wffoT, g_wffoT);

    cudaFuncSetAttribute(attn_mma, cudaFuncAttributeMaxDynamicSharedMemorySize, ATTN_SMEM_DYN);
    cudaFuncSetAttribute(mma_gemm, cudaFuncAttributeMaxDynamicSharedMemorySize, GEMM_SMEM_DYN);

    dim3 tb(32, 8);
    transpose_kernel<<<dim3(3 * EE / 32, EE / 32), tb>>>(w_qkv, wqkvT, EE, 3 * EE);
    mask_kernel<<<MR / 256, 256>>>(am, tt);
    round_kernel<<<(MR * EE / 4) / 256, 256>>>(x, xr, MR * EE / 4);

    // QKV projection (A = rounded x) -> output rounded to tf32 (mode=2)
    mma_gemm<<<dim3(3 * EE / GBN, MR / GBM), 256, GEMM_SMEM_DYN>>>(
        xr, wqkvT, b_qkv, nullptr, qkv, MR, 3 * EE, EE, 2);
    // attention (ctx rounded on store)
    attn_mma<<<dim3(SS / AQ, HH, BB), 256, ATTN_SMEM_DYN>>>(qkv, ctx);

    transpose_kernel<<<dim3(EE / 32, EE / 32), tb>>>(w_out, woutT, EE, EE);
    // out projection + residual (A = rounded ctx, res = original x)
    mma_gemm<<<dim3(EE / GBN, MR / GBM), 256, GEMM_SMEM_DYN>>>(
        ctx, woutT, b_outp, x, t1, MR, EE, EE, 0);
    // LN -> h (+ rounded copy for FFN1 A)
    ln_kernel<<<MR, 256>>>(t1, ln_w, ln_b, hb, hbr);

    transpose_kernel<<<dim3(FF / 32, EE / 32), tb>>>(w_in,  winT,  EE, FF);
    // FFN in + GELU, output rounded (feeds FFN2 A)
    mma_gemm<<<dim3(FF / GBN, MR / GBM), 256, GEMM_SMEM_DYN>>>(
        hbr, winT, b_in, nullptr, ffa, MR, FF, EE, 3);

    transpose_kernel<<<dim3(EE / 32, FF / 32), tb>>>(w_ffo, wffoT, FF, EE);
    // FFN out + residual (A = rounded ffa, res = original h)
    mma_gemm<<<dim3(EE / GBN, MR / GBM), 256, GEMM_SMEM_DYN>>>(
        ffa, wffoT, b_ffo, hb, t2, MR, EE, FF, 0);
    // LN -> out (no rounded copy)
    ln_kernel<<<MR, 256>>>(t2, ln_w, ln_b, out, nullptr);
}

// round 17
// speedup vs baseline: 1.1935x; 1.0350x over previous
#include <cuda_runtime.h>
#include <math.h>
#include <stdint.h>

// Problem constants
#define BB   8
#define SS   1024
#define EE   1024
#define HH   16
#define FF   4096
#define MR   (BB*SS)      // 8192 rows

// -------- scratch (static device globals; no runtime allocation) --------
__device__ float g_qkv[(size_t)MR * 3 * EE];
__device__ float g_ctx[(size_t)MR * EE];
__device__ float g_t1 [(size_t)MR * EE];
__device__ float g_h  [(size_t)MR * EE];
__device__ float g_hr [(size_t)MR * EE];      // tf32-rounded copy of h (GEMM A input)
__device__ float g_xr [(size_t)MR * EE];      // tf32-rounded copy of x (GEMM A input)
__device__ float g_ffa[(size_t)MR * FF];
__device__ float g_t2 [(size_t)MR * EE];
__device__ float g_kadd[MR];
__device__ float g_kneg[MR];
__device__ float g_wqkvT[(size_t)3 * EE * EE];
__device__ float g_woutT[(size_t)EE * EE];
__device__ float g_winT [(size_t)FF * EE];
__device__ float g_wffoT[(size_t)EE * FF];

// ======================= PTX helpers =======================
__device__ __forceinline__ uint32_t smem_u32(const void* p) {
    uint32_t a;
    asm("{ .reg .u64 t; cvta.to.shared.u64 t, %1; cvt.u32.u64 %0, t; }"
        : "=r"(a) : "l"(p));
    return a;
}
__device__ __forceinline__ void cp16(uint32_t dst, const void* src) {
    asm volatile("cp.async.cg.shared.global [%0], [%1], 16;" :: "r"(dst), "l"(src));
}
#define CP_COMMIT() asm volatile("cp.async.commit_group;" ::: "memory")
#define CP_WAIT0()  asm volatile("cp.async.wait_group 0;" ::: "memory")

__device__ __forceinline__ void ldsm4(uint32_t& r0, uint32_t& r1, uint32_t& r2, uint32_t& r3,
                                      uint32_t addr) {
    asm volatile("ldmatrix.sync.aligned.m8n8.x4.shared.b16 {%0,%1,%2,%3}, [%4];"
                 : "=r"(r0), "=r"(r1), "=r"(r2), "=r"(r3) : "r"(addr));
}
__device__ __forceinline__ float rnd_tf32(float v) {
    uint32_t b;
    asm("cvt.rna.tf32.f32 %0, %1;" : "=r"(b) : "f"(v));
    return __uint_as_float(b);
}
__device__ __forceinline__ void mma_tf32(float* c, const uint32_t* a, uint32_t b0, uint32_t b1) {
    asm volatile(
        "mma.sync.aligned.m16n8k8.row.col.f32.tf32.tf32.f32 "
        "{%0,%1,%2,%3}, {%4,%5,%6,%7}, {%8,%9}, {%0,%1,%2,%3};"
        : "+f"(c[0]), "+f"(c[1]), "+f"(c[2]), "+f"(c[3])
        : "r"(a[0]), "r"(a[1]), "r"(a[2]), "r"(a[3]), "r"(b0), "r"(b1));
}

// ======================= weight transpose + tf32 round =======================
__global__ void transpose_kernel(const float* __restrict__ W, float* __restrict__ WT,
                                 int K, int N) {
    __shared__ float t[32][33];
    int n0 = blockIdx.x * 32, k0 = blockIdx.y * 32;
    int tx = threadIdx.x, ty = threadIdx.y;
#pragma unroll
    for (int i = 0; i < 32; i += 8)
        t[ty + i][tx] = W[(size_t)(k0 + ty + i) * N + n0 + tx];
    __syncthreads();
#pragma unroll
    for (int i = 0; i < 32; i += 8) {
        float v = t[tx][ty + i];
        WT[(size_t)(n0 + ty + i) * K + k0 + tx] = rnd_tf32(v);
    }
}

// ======================= elementwise tf32 round (x -> xr) =======================
__global__ void round_kernel(const float* __restrict__ in, float* __restrict__ out, int n4) {
    int i = blockIdx.x * 256 + threadIdx.x;
    if (i >= n4) return;
    float4 v = ((const float4*)in)[i];
    v.x = rnd_tf32(v.x); v.y = rnd_tf32(v.y); v.z = rnd_tf32(v.z); v.w = rnd_tf32(v.w);
    ((float4*)out)[i] = v;
}

// ======================= mask precompute =======================
__global__ void mask_kernel(const int* __restrict__ am, const int* __restrict__ tt) {
    int i = blockIdx.x * 256 + threadIdx.x;
    if (i >= MR) return;
    bool a  = (am[i] != 0);
    bool qm = (tt[i] == 1) || (!a) || ((i & (SS - 1)) == 0);
    g_kadd[i] = a  ? 1.f : 0.f;
    g_kneg[i] = qm ? 1.f : 0.f;
}

// ======================= tf32 tensor-core GEMM v5 (2-tile batched mainloop) =======================
// A inputs MUST be pre-rounded to tf32. 256 thr / 8 warps (2m x 4n), warp tile 64x64.
// 4 stages; loop advances 2 BK-tiles per barrier -> half the sync bubbles, 256-mma runs.
// mode: bit0 = exact GELU; bit1 = round output to tf32
#define GBM 128
#define GBN 256
#define GBK 32
#define GSTAGE_A (GBM * GBK * 4)
#define GSTAGE_B (GBN * GBK * 4)
#define GSTAGE_BYTES (GSTAGE_A + GSTAGE_B)
#define GSTAGES 4
#define GEMM_SMEM_DYN (GSTAGES * GSTAGE_BYTES)   // 192 KB

__global__ __launch_bounds__(256, 1) void mma_gemm(
    const float* __restrict__ A, const float* __restrict__ BT,
    const float* __restrict__ bias, const float* __restrict__ res,
    float* __restrict__ C, int M, int N, int K, int mode)
{
    extern __shared__ char dyn_smem[];
    uint32_t sbase = smem_u32(dyn_smem);
    int tid = threadIdx.x, lane = tid & 31, wid = tid >> 5;
    int wm = wid >> 2, wn = wid & 3;
    int bm = blockIdx.y * GBM, bn = blockIdx.x * GBN;

    float c[4][8][4];
#pragma unroll
    for (int mi = 0; mi < 4; mi++)
#pragma unroll
        for (int j = 0; j < 8; j++)
#pragma unroll
            for (int q = 0; q < 4; q++) c[mi][j][q] = 0.f;

    int T = K / GBK;    // always even (K = 1024 or 4096)

    auto load_tile = [&](int t, int s) {
        int k0 = t * GBK;
        uint32_t sA = sbase + s * GSTAGE_BYTES;
        uint32_t sB = sA + GSTAGE_A;
#pragma unroll
        for (int i = 0; i < 4; i++) {
            int g = tid + i * 256;
            int row = g >> 3, ch = g & 7;
            cp16(sA + row * 128 + ((ch ^ (row & 7)) << 4),
                 A + (size_t)(bm + row) * K + k0 + ch * 4);
        }
#pragma unroll
        for (int i = 0; i < 8; i++) {
            int g = tid + i * 256;
            int row = g >> 3, ch = g & 7;
            cp16(sB + row * 128 + ((ch ^ (row & 7)) << 4),
                 BT + (size_t)(bn + row) * K + k0 + ch * 4);
        }
    };

    load_tile(0, 0); CP_COMMIT();
    load_tile(1, 1); CP_COMMIT();

    for (int t = 0; t < T; t += 2) {
        CP_WAIT0();           // tiles t, t+1 resident
        __syncthreads();      // all warps done reading the stages we overwrite next
        if (t + 2 < T) {
            load_tile(t + 2, (t + 2) & 3); CP_COMMIT();
            load_tile(t + 3, (t + 3) & 3); CP_COMMIT();
        }

#pragma unroll
        for (int u = 0; u < 2; u++) {
            int s = (t + u) & 3;
            uint32_t sA = sbase + s * GSTAGE_BYTES;
            uint32_t sB = sA + GSTAGE_A;

#pragma unroll
            for (int p = 0; p < 2; p++) {
                uint32_t a[4][2][4];
#pragma unroll
                for (int mi = 0; mi < 4; mi++)
#pragma unroll
                    for (int kk = 0; kk < 2; kk++) {
                        int ks = p * 2 + kk;
                        int r = wm * 64 + mi * 16 + ((lane >> 3) & 1) * 8 + (lane & 7);
                        int ch = ks * 2 + (lane >> 4);
                        ldsm4(a[mi][kk][0], a[mi][kk][1], a[mi][kk][2], a[mi][kk][3],
                              sA + r * 128 + ((ch ^ (r & 7)) << 4));
                    }
#pragma unroll
                for (int j = 0; j < 8; j++) {
                    uint32_t b0, b1, b2, b3;
                    int r = wn * 64 + j * 8 + (lane & 7);
                    int ch = p * 4 + (lane >> 3);
                    ldsm4(b0, b1, b2, b3, sB + r * 128 + ((ch ^ (r & 7)) << 4));
#pragma unroll
                    for (int mi = 0; mi < 4; mi++) {
                        mma_tf32(c[mi][j], a[mi][0], b0, b1);
                        mma_tf32(c[mi][j], a[mi][1], b2, b3);
                    }
                }
            }
        }
    }

    // ---- epilogue ----
#pragma unroll
    for (int mi = 0; mi < 4; mi++) {
        int r0 = bm + wm * 64 + mi * 16 + (lane >> 2);
#pragma unroll
        for (int half = 0; half < 2; half++) {
            int r = r0 + half * 8;
            float* Crow = C + (size_t)r * N;
            const float* Rrow = res ? res + (size_t)r * N : nullptr;
#pragma unroll
            for (int j = 0; j < 8; j++) {
                int col = bn + wn * 64 + j * 8 + (lane & 3) * 2;
                float v0 = c[mi][j][half * 2 + 0] + bias[col];
                float v1 = c[mi][j][half * 2 + 1] + bias[col + 1];
                if (Rrow) { v0 += Rrow[col]; v1 += Rrow[col + 1]; }
                if (mode & 1) {
                    v0 = 0.5f * v0 * (1.0f + erff(v0 * 0.70710678118654752f));
                    v1 = 0.5f * v1 * (1.0f + erff(v1 * 0.70710678118654752f));
                }
                if (mode & 2) { v0 = rnd_tf32(v0); v1 = rnd_tf32(v1); }
                *(float2*)(Crow + col) = make_float2(v0, v1);
            }
        }
    }
}

// ======================= Pipelined flash attention (R10/R15; ctx rounded on store) ==========
#define AQ 128
#define AK 64
#define APITCH 68
#define AROW (APITCH * 4)
#define ATTN_SMEM_DYN ((AQ * APITCH + 4 * AK * APITCH) * 4)

__global__ __launch_bounds__(256, 2) void attn_mma(
    const float* __restrict__ QKV, float* __restrict__ CTX)
{
    extern __shared__ float as[];
    float* sQ = as;
    float* sK0 = sQ + AQ * APITCH;
    float* sK1 = sK0 + AK * APITCH;
    float* sV0 = sK1 + AK * APITCH;
    float* sV1 = sV0 + AK * APITCH;
    __shared__ float sAdd[2][AK], sNeg[2][AK];

    uint32_t uQ = smem_u32(sQ);
    uint32_t uK[2] = { smem_u32(sK0), smem_u32(sK1) };
    uint32_t uV[2] = { smem_u32(sV0), smem_u32(sV1) };
    uint32_t uA[2] = { smem_u32(&sAdd[0][0]), smem_u32(&sAdd[1][0]) };
    uint32_t uN[2] = { smem_u32(&sNeg[0][0]), smem_u32(&sNeg[1][0]) };
    float* sVT[2] = { sV0, sV1 };

    int tid = threadIdx.x, lane = tid & 31, wid = tid >> 5;
    int b = blockIdx.z, h = blockIdx.y, q0 = blockIdx.x * AQ;
    int wq0 = wid * 16;

    const float* Qb = QKV + (size_t)b * SS * 3072 + h * 64;
    const float* Kb = Qb + 1024;
    const float* Vb = Qb + 2048;
    const float* madd = g_kadd + b * SS;
    const float* mneg = g_kneg + b * SS;

    int lr = lane >> 2, sub = lane & 3;
    uint32_t qbase = lane & ~3u;
    int phalf = sub >> 1, podd = sub & 1;

    int vg = tid >> 2;
    int vcch = vg & 15;
    int vkb0 = (vg >> 4) << 2;

    // ---------------- prologue ----------------
#pragma unroll
    for (int i = 0; i < 8; i++) {
        int g = tid + i * 256, r = g >> 4, c4 = g & 15;
        cp16(uQ + r * AROW + c4 * 16, Qb + (size_t)(q0 + r) * 3072 + c4 * 4);
    }
#pragma unroll
    for (int i = 0; i < 4; i++) {
        int g = tid + i * 256, r = g >> 4, c4 = g & 15;
        cp16(uK[0] + r * AROW + c4 * 16, Kb + (size_t)r * 3072 + c4 * 4);
    }
    if (tid < 16) cp16(uA[0] + tid * 16, madd + tid * 4);
    else if (tid < 32) cp16(uN[0] + (tid - 16) * 16, mneg + (tid - 16) * 4);
    CP_COMMIT();

    float4 pv[4];
#pragma unroll
    for (int it = 0; it < 4; it++) {
        int kb = vkb0 + (it << 4);
        pv[it] = *(const float4*)(Vb + (size_t)(kb + sub) * 3072 + vcch * 4);
    }

    float amq0 = madd[q0 + wq0 + lr];
    float amq1 = madd[q0 + wq0 + lr + 8];

    CP_WAIT0();
    __syncthreads();

#pragma unroll
    for (int it = 0; it < 4; it++) {
        float a0 = pv[it].x, a1 = pv[it].y, a2 = pv[it].z, a3 = pv[it].w;
        float t0, t1, t2, t3;
#pragma unroll
        for (int j = 0; j < 4; j++) {
            int sidx = (sub + j) & 3;
            float sval = sidx == 0 ? a0 : sidx == 1 ? a1 : sidx == 2 ? a2 : a3;
            int i = (sub - j) & 3;
            float r = __shfl_sync(0xffffffffu, sval, qbase | i);
            if (i == 0) t0 = r; else if (i == 1) t1 = r; else if (i == 2) t2 = r; else t3 = r;
        }
        int d = vcch * 4 + sub;
        int kb = vkb0 + (it << 4);
        *(float4*)(sVT[0] + d * APITCH + kb) = make_float4(t0, t1, t2, t3);
    }
    __syncthreads();

    // ---------------- mainloop ----------------
    float m0 = -INFINITY, m1 = -INFINITY, l0 = 0.f, l1 = 0.f;
    float o[8][4];
#pragma unroll
    for (int j = 0; j < 8; j++)
#pragma unroll
        for (int q = 0; q < 4; q++) o[j][q] = 0.f;

    const int T = SS / AK;
#pragma unroll 1
    for (int t = 0; t < T; t++) {
        int st = t & 1, sn = st ^ 1;
        bool has_next = (t + 1) < T;
        int k0n = has_next ? (t + 1) * AK : 0;

        if (has_next) {
#pragma unroll
            for (int i = 0; i < 4; i++) {
                int g = tid + i * 256, r = g >> 4, c4 = g & 15;
                cp16(uK[sn] + r * AROW + c4 * 16, Kb + (size_t)(k0n + r) * 3072 + c4 * 4);
            }
            if (tid < 16) cp16(uA[sn] + tid * 16, madd + k0n + tid * 4);
            else if (tid < 32) cp16(uN[sn] + (tid - 16) * 16, mneg + k0n + (tid - 16) * 4);
        }
        CP_COMMIT();
        if (has_next) {
#pragma unroll
            for (int it = 0; it < 4; it++) {
                int kb = vkb0 + (it << 4);
                pv[it] = *(const float4*)(Vb + (size_t)(k0n + kb + sub) * 3072 + vcch * 4);
            }
        }

        // ===== S = Q @ K^T =====
        float c[8][4];
#pragma unroll
        for (int j = 0; j < 8; j++)
#pragma unroll
            for (int q = 0; q < 4; q++) c[j][q] = 0.f;

#pragma unroll
        for (int p = 0; p < 4; p++) {
            uint32_t a[2][4];
#pragma unroll
            for (int kk = 0; kk < 2; kk++) {
                int ks = p * 2 + kk;
                int r = wq0 + ((lane >> 3) & 1) * 8 + (lane & 7);
                int ch = ks * 2 + (lane >> 4);
                ldsm4(a[kk][0], a[kk][1], a[kk][2], a[kk][3], uQ + r * AROW + ch * 16);
            }
#pragma unroll
            for (int j = 0; j < 8; j++) {
                uint32_t b0, b1, b2, b3;
                int r = j * 8 + (lane & 7);
                int ch = p * 4 + (lane >> 3);
                ldsm4(b0, b1, b2, b3, uK[st] + r * AROW + ch * 16);
                mma_tf32(c[j], a[0], b0, b1);
                mma_tf32(c[j], a[1], b2, b3);
            }
        }

        // ===== mask + online softmax =====
        float mt0 = -INFINITY, mt1 = -INFINITY;
#pragma unroll
        for (int j = 0; j < 8; j++) {
            int col = j * 8 + sub * 2;
            float ka0 = sAdd[st][col], ka1 = sAdd[st][col + 1];
            float kn0 = sNeg[st][col], kn1 = sNeg[st][col + 1];
            c[j][0] = (kn0 != 0.f) ? -1e30f : c[j][0] * 0.125f + amq0 * ka0;
            c[j][1] = (kn1 != 0.f) ? -1e30f : c[j][1] * 0.125f + amq0 * ka1;
            c[j][2] = (kn0 != 0.f) ? -1e30f : c[j][2] * 0.125f + amq1 * ka0;
            c[j][3] = (kn1 != 0.f) ? -1e30f : c[j][3] * 0.125f + amq1 * ka1;
            mt0 = fmaxf(mt0, fmaxf(c[j][0], c[j][1]));
            mt1 = fmaxf(mt1, fmaxf(c[j][2], c[j][3]));
        }
        mt0 = fmaxf(mt0, __shfl_xor_sync(0xffffffffu, mt0, 1));
        mt0 = fmaxf(mt0, __shfl_xor_sync(0xffffffffu, mt0, 2));
        mt1 = fmaxf(mt1, __shfl_xor_sync(0xffffffffu, mt1, 1));
        mt1 = fmaxf(mt1, __shfl_xor_sync(0xffffffffu, mt1, 2));

        float mn0 = fmaxf(m0, mt0), mn1 = fmaxf(m1, mt1);
        float alpha0 = __expf(m0 - mn0), alpha1 = __expf(m1 - mn1);
        m0 = mn0; m1 = mn1;

        float s0 = 0.f, s1 = 0.f;
#pragma unroll
        for (int j = 0; j < 8; j++) {
            c[j][0] = __expf(c[j][0] - mn0);
            c[j][1] = __expf(c[j][1] - mn0);
            c[j][2] = __expf(c[j][2] - mn1);
            c[j][3] = __expf(c[j][3] - mn1);
            s0 += c[j][0] + c[j][1];
            s1 += c[j][2] + c[j][3];
        }
        s0 += __shfl_xor_sync(0xffffffffu, s0, 1);
        s0 += __shfl_xor_sync(0xffffffffu, s0, 2);
        s1 += __shfl_xor_sync(0xffffffffu, s1, 1);
        s1 += __shfl_xor_sync(0xffffffffu, s1, 2);
        l0 = l0 * alpha0 + s0;
        l1 = l1 * alpha1 + s1;

#pragma unroll
        for (int j = 0; j < 8; j++) {
            o[j][0] *= alpha0; o[j][1] *= alpha0;
            o[j][2] *= alpha1; o[j][3] *= alpha1;
        }

        // ===== O += P @ V =====
#pragma unroll
        for (int p = 0; p < 4; p++) {
            uint32_t a_lo[4], a_hi[4];
#pragma unroll
            for (int hh = 0; hh < 2; hh++) {
                int kc = 2 * p + hh;
                float v00 = __shfl_sync(0xffffffffu, c[kc][0], qbase + phalf);
                float v01 = __shfl_sync(0xffffffffu, c[kc][1], qbase + phalf);
                float v10 = __shfl_sync(0xffffffffu, c[kc][2], qbase + phalf);
                float v11 = __shfl_sync(0xffffffffu, c[kc][3], qbase + phalf);
                float v20 = __shfl_sync(0xffffffffu, c[kc][0], qbase + 2 + phalf);
                float v21 = __shfl_sync(0xffffffffu, c[kc][1], qbase + 2 + phalf);
                float v30 = __shfl_sync(0xffffffffu, c[kc][2], qbase + 2 + phalf);
                float v31 = __shfl_sync(0xffffffffu, c[kc][3], qbase + 2 + phalf);
                uint32_t* a = hh ? a_hi : a_lo;
                a[0] = __float_as_uint(podd ? v01 : v00);
                a[1] = __float_as_uint(podd ? v11 : v10);
                a[2] = __float_as_uint(podd ? v21 : v20);
                a[3] = __float_as_uint(podd ? v31 : v30);
            }
#pragma unroll
            for (int j = 0; j < 8; j++) {
                uint32_t b0, b1, b2, b3;
                int r = j * 8 + (lane & 7);
                int ch = p * 4 + (lane >> 3);
                ldsm4(b0, b1, b2, b3, uV[st] + r * AROW + ch * 16);
                mma_tf32(o[j], a_lo, b0, b1);
                mma_tf32(o[j], a_hi, b2, b3);
            }
        }

        // ===== build VT[t+1] =====
        if (has_next) {
#pragma unroll
            for (int it = 0; it < 4; it++) {
                float a0 = pv[it].x, a1 = pv[it].y, a2 = pv[it].z, a3 = pv[it].w;
                float t0, t1, t2, t3;
#pragma unroll
                for (int j = 0; j < 4; j++) {
                    int sidx = (sub + j) & 3;
                    float sval = sidx == 0 ? a0 : sidx == 1 ? a1 : sidx == 2 ? a2 : a3;
                    int i = (sub - j) & 3;
                    float r = __shfl_sync(0xffffffffu, sval, qbase | i);
                    if (i == 0) t0 = r; else if (i == 1) t1 = r; else if (i == 2) t2 = r; else t3 = r;
                }
                int d = vcch * 4 + sub;
                int kb = vkb0 + (it << 4);
                *(float4*)(sVT[sn] + d * APITCH + kb) = make_float4(t0, t1, t2, t3);
            }
        }

        CP_WAIT0();
        __syncthreads();
    }

    // ---- epilogue: normalize + round to tf32 (ctx only feeds the out-proj GEMM) ----
    float inv0 = 1.f / l0, inv1 = 1.f / l1;
    size_t row0 = (size_t)(b * SS + q0 + wq0 + lr);
    size_t row1 = row0 + 8;
#pragma unroll
    for (int j = 0; j < 8; j++) {
        int col = h * 64 + j * 8 + sub * 2;
        *(float2*)(CTX + row0 * EE + col) =
            make_float2(rnd_tf32(o[j][0] * inv0), rnd_tf32(o[j][1] * inv0));
        *(float2*)(CTX + row1 * EE + col) =
            make_float2(rnd_tf32(o[j][2] * inv1), rnd_tf32(o[j][3] * inv1));
    }
}

// ======================= LayerNorm (optional second rounded output) =======================
__global__ __launch_bounds__(256) void ln_kernel(
    const float* __restrict__ in, const float* __restrict__ w,
    const float* __restrict__ b, float* __restrict__ out,
    float* __restrict__ out_rounded)
{
    int row = blockIdx.x;
    const float* x = in + (size_t)row * EE;
    int tid = threadIdx.x;

    float v[4], s = 0.f, sq = 0.f;
#pragma unroll
    for (int i = 0; i < 4; i++) {
        v[i] = x[tid + i * 256];
        s += v[i];
        sq += v[i] * v[i];
    }
#pragma unroll
    for (int off = 16; off > 0; off >>= 1) {
        s  += __shfl_xor_sync(0xffffffffu, s,  off);
        sq += __shfl_xor_sync(0xffffffffu, sq, off);
    }
    __shared__ float ss[8], ssq[8];
    if ((tid & 31) == 0) { ss[tid >> 5] = s; ssq[tid >> 5] = sq; }
    __syncthreads();
    float ts = 0.f, tsq = 0.f;
#pragma unroll
    for (int wi = 0; wi < 8; wi++) { ts += ss[wi]; tsq += ssq[wi]; }
    float mean = ts * (1.f / EE);
    float var = tsq * (1.f / EE) - mean * mean;
    float rstd = rsqrtf(var + 1e-12f);
    float* y = out + (size_t)row * EE;
    float* yr = out_rounded ? out_rounded + (size_t)row * EE : nullptr;
#pragma unroll
    for (int i = 0; i < 4; i++) {
        int c = tid + i * 256;
        float val = (v[i] - mean) * rstd * w[c] + b[c];
        y[c] = val;
        if (yr) yr[c] = rnd_tf32(val);
    }
}

// ======================= launch =======================
extern "C" void kernel_launch(void* const* d_in, const int* in_sizes, int n_in,
                              void* d_out, int out_size)
{
    const float* x      = (const float*)d_in[0];
    const int*   am     = (const int*)d_in[1];
    const int*   tt     = (const int*)d_in[2];
    const float* w_qkv  = (const float*)d_in[3];
    const float* b_qkv  = (const float*)d_in[4];
    const float* w_out  = (const float*)d_in[5];
    const float* b_outp = (const float*)d_in[6];
    const float* ln_w   = (const float*)d_in[7];
    const float* ln_b   = (const float*)d_in[8];
    const float* w_in   = (const float*)d_in[9];
    const float* b_in   = (const float*)d_in[10];
    const float* w_ffo  = (const float*)d_in[11];
    const float* b_ffo  = (const float*)d_in[12];
    float* out = (float*)d_out;

    float *qkv, *ctx, *t1, *hb, *hbr, *xr, *ffa, *t2, *wqkvT, *woutT, *winT, *wffoT;
    cudaGetSymbolAddress((void**)&qkv,   g_qkv);
    cudaGetSymbolAddress((void**)&ctx,   g_ctx);
    cudaGetSymbolAddress((void**)&t1,    g_t1);
    cudaGetSymbolAddress((void**)&hb,    g_h);
    cudaGetSymbolAddress((void**)&hbr,   g_hr);
    cudaGetSymbolAddress((void**)&xr,    g_xr);
    cudaGetSymbolAddress((void**)&ffa,   g_ffa);
    cudaGetSymbolAddress((void**)&t2,    g_t2);
    cudaGetSymbolAddress((void**)&wqkvT, g_wqkvT);
    cudaGetSymbolAddress((void**)&woutT, g_woutT);
    cudaGetSymbolAddress((void**)&winT,  g_winT);
    cudaGetSymbolAddress((void**)&wffoT, g_wffoT);

    cudaFuncSetAttribute(attn_mma, cudaFuncAttributeMaxDynamicSharedMemorySize, ATTN_SMEM_DYN);
    cudaFuncSetAttribute(mma_gemm, cudaFuncAttributeMaxDynamicSharedMemorySize, GEMM_SMEM_DYN);

    dim3 tb(32, 8);
    transpose_kernel<<<dim3(3 * EE / 32, EE / 32), tb>>>(w_qkv, wqkvT, EE, 3 * EE);
    mask_kernel<<<MR / 256, 256>>>(am, tt);
    round_kernel<<<(MR * EE / 4) / 256, 256>>>(x, xr, MR * EE / 4);

    // QKV projection (A = rounded x) -> output rounded to tf32 (mode=2)
    mma_gemm<<<dim3(3 * EE / GBN, MR / GBM), 256, GEMM_SMEM_DYN>>>(
        xr, wqkvT, b_qkv, nullptr, qkv, MR, 3 * EE, EE, 2);
    // attention (ctx rounded on store)
    attn_mma<<<dim3(SS / AQ, HH, BB), 256, ATTN_SMEM_DYN>>>(qkv, ctx);

    transpose_kernel<<<dim3(EE / 32, EE / 32), tb>>>(w_out, woutT, EE, EE);
    // out projection + residual (A = rounded ctx, res = original x)
    mma_gemm<<<dim3(EE / GBN, MR / GBM), 256, GEMM_SMEM_DYN>>>(
        ctx, woutT, b_outp, x, t1, MR, EE, EE, 0);
    // LN -> h (+ rounded copy for FFN1 A)
    ln_kernel<<<MR, 256>>>(t1, ln_w, ln_b, hb, hbr);

    transpose_kernel<<<dim3(FF / 32, EE / 32), tb>>>(w_in,  winT,  EE, FF);
    // FFN in + GELU, output rounded (feeds FFN2 A)
    mma_gemm<<<dim3(FF / GBN, MR / GBM), 256, GEMM_SMEM_DYN>>>(
        hbr, winT, b_in, nullptr, ffa, MR, FF, EE, 3);

    transpose_kernel<<<dim3(EE / 32, FF / 32), tb>>>(w_ffo, wffoT, FF, EE);
    // FFN out + residual (A = rounded ffa, res = original h)
    mma_gemm<<<dim3(EE / GBN, MR / GBM), 256, GEMM_SMEM_DYN>>>(
        ffa, wffoT, b_ffo, hb, t2, MR, EE, FF, 0);
    // LN -> out (no rounded copy)
    ln_kernel<<<MR, 256>>>(t2, ln_w, ln_b, out, nullptr);
}